// round 6
// baseline (speedup 1.0000x reference)
#include <cuda_runtime.h>
#include <math.h>

// Problem constants: B=32, N=160, C=3, L=128
// SSIM: VALID 11x11 gaussian -> 150x150 output
// STFT: f=12, s=4 -> p=38 patches/dim, bins u,v in 1..5, weight u*v/25

#define SSIM_BLOCKS (5*5*96)   // 25 tiles x (32 b * 3 c) = 2400
#define STFT_BLOCKS (38*32)    // patch rows x batch = 1216
#define TOTAL_BLOCKS (SSIM_BLOCKS + STFT_BLOCKS)

__device__ float g_ssim[SSIM_BLOCKS];
__device__ float g_stft[STFT_BLOCKS];
__device__ unsigned int g_count = 0;   // completion counter (reset by last block)

// gaussian weights (normalized), compile-time immediates
__device__ __forceinline__ constexpr float GNW(int k) {
    constexpr float g[11] = {0.00102838f, 0.00759887f, 0.03600077f, 0.10936069f,
                             0.21300553f, 0.26601172f, 0.21300553f, 0.10936069f,
                             0.03600077f, 0.00759887f, 0.00102838f};
    return g[k];
}

__device__ __forceinline__ constexpr float cw12f(int k) {
    constexpr float t[12] = { 1.f, 0.86602540378f, 0.5f, 0.f, -0.5f, -0.86602540378f,
                             -1.f,-0.86602540378f,-0.5f, 0.f,  0.5f,  0.86602540378f};
    return t[k];
}
__device__ __forceinline__ constexpr float sw12f(int k) {
    constexpr float t[12] = { 0.f, 0.5f, 0.86602540378f, 1.f, 0.86602540378f, 0.5f,
                              0.f,-0.5f,-0.86602540378f,-1.f,-0.86602540378f,-0.5f};
    return t[k];
}

// 12-point real-input DFT, bins u=1..5, hand-factored
__device__ __forceinline__ void dft12_5(const float* __restrict__ v,
                                        float* __restrict__ hr,
                                        float* __restrict__ hi)
{
    const float S3 = 0.86602540378f;
    float A1 = v[1]-v[5]-v[7]+v[11];
    float B1 = v[2]-v[4]-v[8]+v[10];
    float D1 = v[0]-v[6];
    float A2 = v[1]+v[5]-v[7]-v[11];
    float B2 = v[2]+v[4]-v[8]-v[10];
    float D2 = v[3]-v[9];
    float t1 = S3*A1, t2 = 0.5f*B1;
    float s1 = 0.5f*A2, s2 = S3*B2;
    hr[0] = D1 + t1 + t2;            hi[0] = -(s1 + s2 + D2);   // u=1
    hr[4] = D1 - t1 + t2;            hi[4] = -(s1 - s2 + D2);   // u=5
    float p0 = v[0]+v[6], p3 = v[3]+v[9];
    float q1 = v[1]+v[7], q2 = v[2]+v[8], q4 = v[4]+v[10], q5 = v[5]+v[11];
    hr[1] = (p0 - p3) + 0.5f*((q1+q5) - (q2+q4));               // u=2
    hi[1] = -S3*((q1+q2) - (q4+q5));
    hr[2] = (v[0]+v[4]+v[8]) - (v[2]+v[6]+v[10]);               // u=3
    hi[2] = (v[3]+v[7]+v[11]) - (v[1]+v[5]+v[9]);
    float E0 = p0+p3, E1 = q1+q4, E2 = q2+q5;
    hr[3] = E0 - 0.5f*(E1+E2);                                  // u=4
    hi[3] = -S3*(E1-E2);
}

__device__ __forceinline__ float fast_atan2f(float y, float x) {
    float ax = fabsf(x), ay = fabsf(y);
    float mx = fmaxf(ax, ay), mn = fminf(ax, ay);
    float t = __fdividef(mn, mx);
    float s = t*t;
    float p =             -0.01172120f;
    p = fmaf(p, s,         0.05265332f);
    p = fmaf(p, s,        -0.11643287f);
    p = fmaf(p, s,         0.19354346f);
    p = fmaf(p, s,        -0.33262347f);
    p = fmaf(p, s,         0.99997726f);
    float r = p * t;
    if (ay > ax)  r = 1.57079632679f - r;
    if (x < 0.f)  r = 3.14159265359f - r;
    return copysignf(r, y);
}

// ---------------------------------------------------------------------------
// Fused compute kernel: bid < STFT_BLOCKS -> stft work; else ssim work.
// Last block to finish performs the final fixed-order fp64 reduction
// (threadfence-reduction pattern; fence from ONE thread per block only —
// gpu-scope fences emit CCTL.IVALL (L1 flush) on sm_103a, so per-thread
// fencing is catastrophic).
// ---------------------------------------------------------------------------
union SmemU {
    float  red[256];                      // aliases the fronts (sync-guarded)
    double dred[256];                     // final-reduction buffer (last block)
    struct {
        ulonglong2 H[5][540];             // [u][swizzled col] = {reI,imI,reO,imO}
    } stft;
    struct {
        float2 sxy[42][45];               // (x,y) pixel pairs
        float2 hA[42][33];                // (hx, hy)
        float2 hB[42][33];                // (h_{xx+yy}, h_xy)
    } ssim;
};

__global__ void __launch_bounds__(256, 4) fused_kernel(const float* __restrict__ xin,
                                                       const float* __restrict__ xout,
                                                       const float* __restrict__ mean,
                                                       const float* __restrict__ logvar,
                                                       float* __restrict__ out)
{
    __shared__ SmemU S;
    __shared__ bool s_isLast;
    const int tid = threadIdx.x;
    const int bid = blockIdx.x;

    if (bid < STFT_BLOCKS) {
        // =================== STFT path ===================
        const int b = bid / 38;
        const int prow = bid - b * 38;    // image rows prow*4 .. prow*4+11

        const float* pin  = xin  + ((long)b * 160 + (long)prow * 4) * 480;
        const float* pout = xout + ((long)b * 160 + (long)prow * 4) * 480;

        // Phase A: column DFTs straight from gmem (coalesced across lanes)
        for (int e = tid; e < 480; e += 256) {
            float vi[12], vo[12];
            #pragma unroll
            for (int y = 0; y < 12; y++) {
                vi[y] = pin [y*480 + e];
                vo[y] = pout[y*480 + e];
            }
            float hir[5], hii[5], hor[5], hoi[5];
            dft12_5(vi, hir, hii);
            dft12_5(vo, hor, hoi);
            const int es = e + (e >> 3);  // bank swizzle
            #pragma unroll
            for (int u = 0; u < 5; u++) {
                float4 f = make_float4(hir[u], hii[u], hor[u], hoi[u]);
                S.stft.H[u][es] = *reinterpret_cast<ulonglong2*>(&f);
            }
        }
        __syncthreads();

        // Phase B: 570 items = 38 patches x 3 ch x 5 u
        float acc = 0.f;
        for (int id = tid; id < 570; id += 256) {
            const int u = id / 114;       // 0..4  (bin u+1)
            const int m = id - u*114;     // 0..113 = j*3 + c
            const int cch = m % 3;
            const int ebase = 4*m - 3*cch;  // = 12j + c

            float Fir[5], Fii[5], For[5], Foi[5];
            #pragma unroll
            for (int v = 0; v < 5; v++) { Fir[v]=0.f; Fii[v]=0.f; For[v]=0.f; Foi[v]=0.f; }

            #pragma unroll
            for (int x = 0; x < 12; x++) {
                const int e = ebase + 3*x;
                const int es = e + (e >> 3);
                ulonglong2 hraw = S.stft.H[u][es];
                float4 h = *reinterpret_cast<float4*>(&hraw);
                #pragma unroll
                for (int v = 1; v <= 5; v++) {
                    const int k = (v*x) % 12;
                    const float c_ = cw12f(k), s_ = sw12f(k);
                    const int vi = v - 1;
                    if (s_ == 0.f) {
                        if (c_ > 0.f) { Fir[vi]+=h.x; Fii[vi]+=h.y; For[vi]+=h.z; Foi[vi]+=h.w; }
                        else          { Fir[vi]-=h.x; Fii[vi]-=h.y; For[vi]-=h.z; Foi[vi]-=h.w; }
                    } else if (c_ == 0.f) {
                        if (s_ > 0.f) { Fir[vi]+=h.y; Fii[vi]-=h.x; For[vi]+=h.w; Foi[vi]-=h.z; }
                        else          { Fir[vi]-=h.y; Fii[vi]+=h.x; For[vi]-=h.w; Foi[vi]+=h.z; }
                    } else {
                        Fir[vi] = fmaf(h.x,  c_, fmaf(h.y,  s_, Fir[vi]));
                        Fii[vi] = fmaf(h.y,  c_, fmaf(h.x, -s_, Fii[vi]));
                        For[vi] = fmaf(h.z,  c_, fmaf(h.w,  s_, For[vi]));
                        Foi[vi] = fmaf(h.w,  c_, fmaf(h.z, -s_, Foi[vi]));
                    }
                }
            }

            const float wu = (float)(u + 1) * (1.f / 25.f);
            #pragma unroll
            for (int v = 1; v <= 5; v++) {
                const int vi = v - 1;
                float angi = fast_atan2f(Fii[vi], Fir[vi] + 1e-8f);
                float ango = fast_atan2f(Foi[vi], For[vi] + 1e-8f);
                float m2i = fmaf(Fir[vi], Fir[vi], Fii[vi]*Fii[vi]);
                float m2o = fmaf(For[vi], For[vi], Foi[vi]*Foi[vi]);
                float magi = m2i * __frsqrt_rn(fmaxf(m2i, 1e-30f));
                float mago = m2o * __frsqrt_rn(fmaxf(m2o, 1e-30f));
                acc = fmaf((float)v * wu, fabsf(ango - angi) + fabsf(mago - magi), acc);
            }
        }

        __syncthreads();                  // red aliases H: all reads must finish
        S.red[tid] = acc;
        __syncthreads();
        #pragma unroll
        for (int s = 128; s > 0; s >>= 1) {
            if (tid < s) S.red[tid] += S.red[tid + s];
            __syncthreads();
        }
        if (tid == 0)
            g_stft[bid] = S.red[0];

    } else {
        // =================== SSIM path ===================
        const int idx = bid - STFT_BLOCKS;
        const int bz = idx / 25;          // b*3 + c
        const int r25 = idx - bz*25;
        const int by = r25 / 5, bx = r25 - by*5;
        const int c  = bz % 3, b = bz / 3;
        const int ox = bx * 32, oy = by * 32;

        const float* pin  = xin  + (size_t)b * (160*160*3) + c;
        const float* pout = xout + (size_t)b * (160*160*3) + c;

        // load 42x42 input tile (halo), zero-pad OOB (those outputs masked)
        for (int i = tid; i < 42*42; i += 256) {
            int r = i / 42, cc = i - r*42;
            int gr = oy + r, gc = ox + cc;
            float vx = 0.f, vy = 0.f;
            if (gr < 160 && gc < 160) {
                size_t off = ((size_t)gr*160 + gc) * 3;
                vx = pin[off]; vy = pout[off];
            }
            S.ssim.sxy[r][cc] = make_float2(vx, vy);
        }
        __syncthreads();

        // horizontal pass: 42 rows x 8 groups of 4 cols, k-outer
        for (int i = tid; i < 42*8; i += 256) {
            int r = i >> 3, c0 = (i & 7) * 4;
            float2 A[4], Bv[4];
            #pragma unroll
            for (int g = 0; g < 4; g++) { A[g] = make_float2(0.f,0.f); Bv[g] = make_float2(0.f,0.f); }
            #pragma unroll
            for (int k = 0; k < 14; k++) {
                float2 xy = S.ssim.sxy[r][c0 + k];
                float ss = fmaf(xy.y, xy.y, xy.x*xy.x);
                float ad = xy.x * xy.y;
                #pragma unroll
                for (int g = 0; g < 4; g++) {
                    const int kk = k - g;
                    if (kk >= 0 && kk < 11) {
                        const float w = GNW(kk);
                        A[g].x  = fmaf(w, xy.x, A[g].x);
                        A[g].y  = fmaf(w, xy.y, A[g].y);
                        Bv[g].x = fmaf(w, ss,   Bv[g].x);
                        Bv[g].y = fmaf(w, ad,   Bv[g].y);
                    }
                }
            }
            #pragma unroll
            for (int g = 0; g < 4; g++) {
                S.ssim.hA[r][c0 + g] = A[g];
                S.ssim.hB[r][c0 + g] = Bv[g];
            }
        }
        __syncthreads();

        // vertical pass: 32 cols x 8 row-groups, 4 outputs/thread, k-outer
        const int tx = tid & 31, ty = tid >> 5;
        const int rb = ty * 4;

        float2 aA[4], aB[4];
        #pragma unroll
        for (int g = 0; g < 4; g++) { aA[g] = make_float2(0.f,0.f); aB[g] = make_float2(0.f,0.f); }

        #pragma unroll
        for (int k = 0; k < 14; k++) {
            float2 tA = S.ssim.hA[rb + k][tx];
            float2 tB = S.ssim.hB[rb + k][tx];
            #pragma unroll
            for (int g = 0; g < 4; g++) {
                const int kk = k - g;
                if (kk >= 0 && kk < 11) {
                    const float w = GNW(kk);
                    aA[g].x = fmaf(w, tA.x, aA[g].x);
                    aA[g].y = fmaf(w, tA.y, aA[g].y);
                    aB[g].x = fmaf(w, tB.x, aB[g].x);
                    aB[g].y = fmaf(w, tB.y, aB[g].y);
                }
            }
        }

        float val = 0.f;
        const int gx = ox + tx;
        #pragma unroll
        for (int g = 0; g < 4; g++) {
            int gy = oy + rb + g;
            if (gx < 150 && gy < 150) {
                const float C1 = 1e-4f, C2 = 9e-4f;
                float mx = aA[g].x, my = aA[g].y;
                float vsum = aB[g].x - mx*mx - my*my;   // var_x + var_y
                float cov  = aB[g].y - mx*my;
                float lum = __fdividef(2.f*mx*my + C1, mx*mx + my*my + C1);
                float cs  = __fdividef(2.f*cov + C2, vsum + C2);
                val = fmaf(lum, cs, val);
            }
        }

        S.red[tid] = val;
        __syncthreads();
        #pragma unroll
        for (int s = 128; s > 0; s >>= 1) {
            if (tid < s) S.red[tid] += S.red[tid + s];
            __syncthreads();
        }
        if (tid == 0)
            g_ssim[idx] = S.red[0];
    }

    // =================== last-block final reduction ===================
    // Fence + counter from thread 0 ONLY (gpu-scope fence flushes L1D on
    // sm_103a; per-thread fencing cost ~20us in R5).
    if (tid == 0) {
        __threadfence();                  // publish this block's g_* write
        unsigned int old = atomicAdd(&g_count, 1u);
        s_isLast = (old == TOTAL_BLOCKS - 1);
    }
    __syncthreads();

    if (s_isLast) {
        const double K_KLD  = -0.5 / 32.0;
        const double K_SSIM = 1.0 / (32.0 * 150.0 * 150.0 * 3.0);
        const double K_STFT = 1e-4 / 32.0;

        double acc = 0.0;
        for (int i = tid; i < 32*128; i += 256) {
            float lv = logvar[i], m = mean[i];
            acc += (double)(1.0f + lv - expf(lv) - m*m) * K_KLD;
        }
        for (int i = tid; i < SSIM_BLOCKS; i += 256)
            acc += (double)__ldcg(&g_ssim[i]) * K_SSIM;
        for (int i = tid; i < STFT_BLOCKS; i += 256)
            acc += (double)__ldcg(&g_stft[i]) * K_STFT;

        __syncthreads();                  // smem reuse guard
        S.dred[tid] = acc;
        __syncthreads();
        #pragma unroll
        for (int s = 128; s > 0; s >>= 1) {
            if (tid < s) S.dred[tid] += S.dred[tid + s];
            __syncthreads();
        }
        if (tid == 0) {
            out[0] = (float)S.dred[0];
            g_count = 0;                  // reset for next graph replay
        }
    }
}

// ---------------------------------------------------------------------------
extern "C" void kernel_launch(void* const* d_in, const int* in_sizes, int n_in,
                              void* d_out, int out_size)
{
    const float* mean   = (const float*)d_in[0];
    const float* logvar = (const float*)d_in[1];
    const float* xin    = (const float*)d_in[2];
    const float* xout   = (const float*)d_in[3];
    float* out = (float*)d_out;

    fused_kernel<<<TOTAL_BLOCKS, 256>>>(xin, xout, mean, logvar, out);
}

// round 7
// speedup vs baseline: 1.1524x; 1.1524x over previous
#include <cuda_runtime.h>
#include <math.h>

// Problem constants: B=32, N=160, C=3, L=128
// SSIM: VALID 11x11 gaussian -> 150x150 output
// STFT: f=12, s=4 -> p=38 patches/dim, bins u,v in 1..5, weight u*v/25

#define SSIM_BLOCKS (5*5*96)   // 25 tiles x (32 b * 3 c) = 2400
#define STFT_BLOCKS (38*32)    // patch rows x batch = 1216
#define TOTAL_BLOCKS (SSIM_BLOCKS + STFT_BLOCKS)

__device__ float g_ssim[SSIM_BLOCKS];
__device__ float g_stft[STFT_BLOCKS];

// gaussian weights (normalized), compile-time immediates
__device__ __forceinline__ constexpr float GNW(int k) {
    constexpr float g[11] = {0.00102838f, 0.00759887f, 0.03600077f, 0.10936069f,
                             0.21300553f, 0.26601172f, 0.21300553f, 0.10936069f,
                             0.03600077f, 0.00759887f, 0.00102838f};
    return g[k];
}

__device__ __forceinline__ constexpr float cw12f(int k) {
    constexpr float t[12] = { 1.f, 0.86602540378f, 0.5f, 0.f, -0.5f, -0.86602540378f,
                             -1.f,-0.86602540378f,-0.5f, 0.f,  0.5f,  0.86602540378f};
    return t[k];
}
__device__ __forceinline__ constexpr float sw12f(int k) {
    constexpr float t[12] = { 0.f, 0.5f, 0.86602540378f, 1.f, 0.86602540378f, 0.5f,
                              0.f,-0.5f,-0.86602540378f,-1.f,-0.86602540378f,-0.5f};
    return t[k];
}

// 12-point real-input DFT, bins u=1..5, hand-factored
__device__ __forceinline__ void dft12_5(const float* __restrict__ v,
                                        float* __restrict__ hr,
                                        float* __restrict__ hi)
{
    const float S3 = 0.86602540378f;
    float A1 = v[1]-v[5]-v[7]+v[11];
    float B1 = v[2]-v[4]-v[8]+v[10];
    float D1 = v[0]-v[6];
    float A2 = v[1]+v[5]-v[7]-v[11];
    float B2 = v[2]+v[4]-v[8]-v[10];
    float D2 = v[3]-v[9];
    float t1 = S3*A1, t2 = 0.5f*B1;
    float s1 = 0.5f*A2, s2 = S3*B2;
    hr[0] = D1 + t1 + t2;            hi[0] = -(s1 + s2 + D2);   // u=1
    hr[4] = D1 - t1 + t2;            hi[4] = -(s1 - s2 + D2);   // u=5
    float p0 = v[0]+v[6], p3 = v[3]+v[9];
    float q1 = v[1]+v[7], q2 = v[2]+v[8], q4 = v[4]+v[10], q5 = v[5]+v[11];
    hr[1] = (p0 - p3) + 0.5f*((q1+q5) - (q2+q4));               // u=2
    hi[1] = -S3*((q1+q2) - (q4+q5));
    hr[2] = (v[0]+v[4]+v[8]) - (v[2]+v[6]+v[10]);               // u=3
    hi[2] = (v[3]+v[7]+v[11]) - (v[1]+v[5]+v[9]);
    float E0 = p0+p3, E1 = q1+q4, E2 = q2+q5;
    hr[3] = E0 - 0.5f*(E1+E2);                                  // u=4
    hi[3] = -S3*(E1-E2);
}

__device__ __forceinline__ float fast_atan2f(float y, float x) {
    float ax = fabsf(x), ay = fabsf(y);
    float mx = fmaxf(ax, ay), mn = fminf(ax, ay);
    float t = __fdividef(mn, mx);
    float s = t*t;
    float p =             -0.01172120f;
    p = fmaf(p, s,         0.05265332f);
    p = fmaf(p, s,        -0.11643287f);
    p = fmaf(p, s,         0.19354346f);
    p = fmaf(p, s,        -0.33262347f);
    p = fmaf(p, s,         0.99997726f);
    float r = p * t;
    if (ay > ax)  r = 1.57079632679f - r;
    if (x < 0.f)  r = 3.14159265359f - r;
    return copysignf(r, y);
}

// ---------------------------------------------------------------------------
// Fused compute kernel: bid < STFT_BLOCKS -> stft work; else ssim work.
// __launch_bounds__(256, 5): cap regs at 51 so 5 blocks/SM fit (regs AND
// smem 43.2KB x 5 = 216KB <= 227KB). R5/R6 showed 56 regs -> 4 blocks only.
// ---------------------------------------------------------------------------
union SmemU {
    float red[256];                       // aliases the fronts (sync-guarded)
    struct {
        ulonglong2 H[5][540];             // [u][swizzled col] = {reI,imI,reO,imO}
    } stft;
    struct {
        float2 sxy[42][45];               // (x,y) pixel pairs
        float2 hA[42][33];                // (hx, hy)
        float2 hB[42][33];                // (h_{xx+yy}, h_xy)
    } ssim;
};

__global__ void __launch_bounds__(256, 5) fused_kernel(const float* __restrict__ xin,
                                                       const float* __restrict__ xout)
{
    __shared__ SmemU S;
    const int tid = threadIdx.x;
    const int bid = blockIdx.x;

    if (bid < STFT_BLOCKS) {
        // =================== STFT path ===================
        const int b = bid / 38;
        const int prow = bid - b * 38;    // image rows prow*4 .. prow*4+11

        const float* pin  = xin  + ((long)b * 160 + (long)prow * 4) * 480;
        const float* pout = xout + ((long)b * 160 + (long)prow * 4) * 480;

        // Phase A: column DFTs straight from gmem (coalesced across lanes)
        for (int e = tid; e < 480; e += 256) {
            float vi[12], vo[12];
            #pragma unroll
            for (int y = 0; y < 12; y++) {
                vi[y] = pin [y*480 + e];
                vo[y] = pout[y*480 + e];
            }
            float hir[5], hii[5], hor[5], hoi[5];
            dft12_5(vi, hir, hii);
            dft12_5(vo, hor, hoi);
            const int es = e + (e >> 3);  // bank swizzle
            #pragma unroll
            for (int u = 0; u < 5; u++) {
                float4 f = make_float4(hir[u], hii[u], hor[u], hoi[u]);
                S.stft.H[u][es] = *reinterpret_cast<ulonglong2*>(&f);
            }
        }
        __syncthreads();

        // Phase B: 570 items = 38 patches x 3 ch x 5 u
        float acc = 0.f;
        for (int id = tid; id < 570; id += 256) {
            const int u = id / 114;       // 0..4  (bin u+1)
            const int m = id - u*114;     // 0..113 = j*3 + c
            const int cch = m % 3;
            const int ebase = 4*m - 3*cch;  // = 12j + c

            float Fir[5], Fii[5], For[5], Foi[5];
            #pragma unroll
            for (int v = 0; v < 5; v++) { Fir[v]=0.f; Fii[v]=0.f; For[v]=0.f; Foi[v]=0.f; }

            #pragma unroll
            for (int x = 0; x < 12; x++) {
                const int e = ebase + 3*x;
                const int es = e + (e >> 3);
                ulonglong2 hraw = S.stft.H[u][es];
                float4 h = *reinterpret_cast<float4*>(&hraw);
                #pragma unroll
                for (int v = 1; v <= 5; v++) {
                    const int k = (v*x) % 12;
                    const float c_ = cw12f(k), s_ = sw12f(k);
                    const int vi = v - 1;
                    if (s_ == 0.f) {
                        if (c_ > 0.f) { Fir[vi]+=h.x; Fii[vi]+=h.y; For[vi]+=h.z; Foi[vi]+=h.w; }
                        else          { Fir[vi]-=h.x; Fii[vi]-=h.y; For[vi]-=h.z; Foi[vi]-=h.w; }
                    } else if (c_ == 0.f) {
                        if (s_ > 0.f) { Fir[vi]+=h.y; Fii[vi]-=h.x; For[vi]+=h.w; Foi[vi]-=h.z; }
                        else          { Fir[vi]-=h.y; Fii[vi]+=h.x; For[vi]-=h.w; Foi[vi]+=h.z; }
                    } else {
                        Fir[vi] = fmaf(h.x,  c_, fmaf(h.y,  s_, Fir[vi]));
                        Fii[vi] = fmaf(h.y,  c_, fmaf(h.x, -s_, Fii[vi]));
                        For[vi] = fmaf(h.z,  c_, fmaf(h.w,  s_, For[vi]));
                        Foi[vi] = fmaf(h.w,  c_, fmaf(h.z, -s_, Foi[vi]));
                    }
                }
            }

            const float wu = (float)(u + 1) * (1.f / 25.f);
            #pragma unroll
            for (int v = 1; v <= 5; v++) {
                const int vi = v - 1;
                float angi = fast_atan2f(Fii[vi], Fir[vi] + 1e-8f);
                float ango = fast_atan2f(Foi[vi], For[vi] + 1e-8f);
                float m2i = fmaf(Fir[vi], Fir[vi], Fii[vi]*Fii[vi]);
                float m2o = fmaf(For[vi], For[vi], Foi[vi]*Foi[vi]);
                float magi = m2i * __frsqrt_rn(fmaxf(m2i, 1e-30f));
                float mago = m2o * __frsqrt_rn(fmaxf(m2o, 1e-30f));
                acc = fmaf((float)v * wu, fabsf(ango - angi) + fabsf(mago - magi), acc);
            }
        }

        __syncthreads();                  // red aliases H: all reads must finish
        S.red[tid] = acc;
        __syncthreads();
        #pragma unroll
        for (int s = 128; s > 0; s >>= 1) {
            if (tid < s) S.red[tid] += S.red[tid + s];
            __syncthreads();
        }
        if (tid == 0)
            g_stft[bid] = S.red[0];

    } else {
        // =================== SSIM path ===================
        const int idx = bid - STFT_BLOCKS;
        const int bz = idx / 25;          // b*3 + c
        const int r25 = idx - bz*25;
        const int by = r25 / 5, bx = r25 - by*5;
        const int c  = bz % 3, b = bz / 3;
        const int ox = bx * 32, oy = by * 32;

        const float* pin  = xin  + (size_t)b * (160*160*3) + c;
        const float* pout = xout + (size_t)b * (160*160*3) + c;

        // load 42x42 input tile (halo), zero-pad OOB (those outputs masked)
        for (int i = tid; i < 42*42; i += 256) {
            int r = i / 42, cc = i - r*42;
            int gr = oy + r, gc = ox + cc;
            float vx = 0.f, vy = 0.f;
            if (gr < 160 && gc < 160) {
                size_t off = ((size_t)gr*160 + gc) * 3;
                vx = pin[off]; vy = pout[off];
            }
            S.ssim.sxy[r][cc] = make_float2(vx, vy);
        }
        __syncthreads();

        // horizontal pass: 42 rows x 8 groups of 4 cols, k-outer
        for (int i = tid; i < 42*8; i += 256) {
            int r = i >> 3, c0 = (i & 7) * 4;
            float2 A[4], Bv[4];
            #pragma unroll
            for (int g = 0; g < 4; g++) { A[g] = make_float2(0.f,0.f); Bv[g] = make_float2(0.f,0.f); }
            #pragma unroll
            for (int k = 0; k < 14; k++) {
                float2 xy = S.ssim.sxy[r][c0 + k];
                float ss = fmaf(xy.y, xy.y, xy.x*xy.x);
                float ad = xy.x * xy.y;
                #pragma unroll
                for (int g = 0; g < 4; g++) {
                    const int kk = k - g;
                    if (kk >= 0 && kk < 11) {
                        const float w = GNW(kk);
                        A[g].x  = fmaf(w, xy.x, A[g].x);
                        A[g].y  = fmaf(w, xy.y, A[g].y);
                        Bv[g].x = fmaf(w, ss,   Bv[g].x);
                        Bv[g].y = fmaf(w, ad,   Bv[g].y);
                    }
                }
            }
            #pragma unroll
            for (int g = 0; g < 4; g++) {
                S.ssim.hA[r][c0 + g] = A[g];
                S.ssim.hB[r][c0 + g] = Bv[g];
            }
        }
        __syncthreads();

        // vertical pass: 32 cols x 8 row-groups, 4 outputs/thread, k-outer
        const int tx = tid & 31, ty = tid >> 5;
        const int rb = ty * 4;

        float2 aA[4], aB[4];
        #pragma unroll
        for (int g = 0; g < 4; g++) { aA[g] = make_float2(0.f,0.f); aB[g] = make_float2(0.f,0.f); }

        #pragma unroll
        for (int k = 0; k < 14; k++) {
            float2 tA = S.ssim.hA[rb + k][tx];
            float2 tB = S.ssim.hB[rb + k][tx];
            #pragma unroll
            for (int g = 0; g < 4; g++) {
                const int kk = k - g;
                if (kk >= 0 && kk < 11) {
                    const float w = GNW(kk);
                    aA[g].x = fmaf(w, tA.x, aA[g].x);
                    aA[g].y = fmaf(w, tA.y, aA[g].y);
                    aB[g].x = fmaf(w, tB.x, aB[g].x);
                    aB[g].y = fmaf(w, tB.y, aB[g].y);
                }
            }
        }

        float val = 0.f;
        const int gx = ox + tx;
        #pragma unroll
        for (int g = 0; g < 4; g++) {
            int gy = oy + rb + g;
            if (gx < 150 && gy < 150) {
                const float C1 = 1e-4f, C2 = 9e-4f;
                float mx = aA[g].x, my = aA[g].y;
                float vsum = aB[g].x - mx*mx - my*my;   // var_x + var_y
                float cov  = aB[g].y - mx*my;
                float lum = __fdividef(2.f*mx*my + C1, mx*mx + my*my + C1);
                float cs  = __fdividef(2.f*cov + C2, vsum + C2);
                val = fmaf(lum, cs, val);
            }
        }

        S.red[tid] = val;
        __syncthreads();
        #pragma unroll
        for (int s = 128; s > 0; s >>= 1) {
            if (tid < s) S.red[tid] += S.red[tid + s];
            __syncthreads();
        }
        if (tid == 0)
            g_ssim[idx] = S.red[0];
    }
}

// ---------------------------------------------------------------------------
// Final kernel: deterministic fixed-order fp64 reduction, warp-shuffle tree
// (2 barriers instead of 9). Order fixed -> bitwise deterministic.
// loss = mean_b( -0.5*sum(1+lv-e^lv-m^2) + ssim_mean + 1e-4*stft_sum )
// ---------------------------------------------------------------------------
__global__ void __launch_bounds__(512) final_kernel(const float* __restrict__ mean,
                                                    const float* __restrict__ logvar,
                                                    float* __restrict__ out)
{
    __shared__ double warpsum[16];
    const int tid = threadIdx.x;
    double acc = 0.0;

    const double K_KLD  = -0.5 / 32.0;
    const double K_SSIM = 1.0 / (32.0 * 150.0 * 150.0 * 3.0);
    const double K_STFT = 1e-4 / 32.0;

    for (int i = tid; i < 32*128; i += 512) {
        float lv = logvar[i], m = mean[i];
        acc += (double)(1.0f + lv - expf(lv) - m*m) * K_KLD;
    }
    for (int i = tid; i < SSIM_BLOCKS; i += 512)
        acc += (double)__ldcg(&g_ssim[i]) * K_SSIM;
    for (int i = tid; i < STFT_BLOCKS; i += 512)
        acc += (double)__ldcg(&g_stft[i]) * K_STFT;

    // warp-level fp64 shuffle reduction (fixed tree order)
    #pragma unroll
    for (int off = 16; off > 0; off >>= 1)
        acc += __shfl_down_sync(0xffffffffu, acc, off);
    if ((tid & 31) == 0) warpsum[tid >> 5] = acc;
    __syncthreads();

    if (tid < 32) {
        double v = (tid < 16) ? warpsum[tid] : 0.0;
        #pragma unroll
        for (int off = 8; off > 0; off >>= 1)
            v += __shfl_down_sync(0xffffffffu, v, off);
        if (tid == 0) out[0] = (float)v;
    }
}

// ---------------------------------------------------------------------------
extern "C" void kernel_launch(void* const* d_in, const int* in_sizes, int n_in,
                              void* d_out, int out_size)
{
    const float* mean   = (const float*)d_in[0];
    const float* logvar = (const float*)d_in[1];
    const float* xin    = (const float*)d_in[2];
    const float* xout   = (const float*)d_in[3];
    float* out = (float*)d_out;

    fused_kernel<<<TOTAL_BLOCKS, 256>>>(xin, xout);
    final_kernel<<<1, 512>>>(mean, logvar, out);
}

// round 8
// speedup vs baseline: 1.1929x; 1.0351x over previous
#include <cuda_runtime.h>
#include <math.h>

// Problem constants: B=32, N=160, C=3, L=128
// SSIM: VALID 11x11 gaussian -> 150x150 output
// STFT: f=12, s=4 -> p=38 patches/dim, bins u,v in 1..5, weight u*v/25

#define SSIM_BLOCKS (5*5*96)   // 25 tiles x (32 b * 3 c) = 2400
#define STFT_BLOCKS (38*32)    // patch rows x batch = 1216
#define TOTAL_BLOCKS (SSIM_BLOCKS + STFT_BLOCKS)

__device__ float g_ssim[SSIM_BLOCKS];
__device__ float g_stft[STFT_BLOCKS];

// gaussian weights (normalized), compile-time immediates
__device__ __forceinline__ constexpr float GNW(int k) {
    constexpr float g[11] = {0.00102838f, 0.00759887f, 0.03600077f, 0.10936069f,
                             0.21300553f, 0.26601172f, 0.21300553f, 0.10936069f,
                             0.03600077f, 0.00759887f, 0.00102838f};
    return g[k];
}

__device__ __forceinline__ constexpr float cw12f(int k) {
    constexpr float t[12] = { 1.f, 0.86602540378f, 0.5f, 0.f, -0.5f, -0.86602540378f,
                             -1.f,-0.86602540378f,-0.5f, 0.f,  0.5f,  0.86602540378f};
    return t[k];
}
__device__ __forceinline__ constexpr float sw12f(int k) {
    constexpr float t[12] = { 0.f, 0.5f, 0.86602540378f, 1.f, 0.86602540378f, 0.5f,
                              0.f,-0.5f,-0.86602540378f,-1.f,-0.86602540378f,-0.5f};
    return t[k];
}

// 12-point real-input DFT, bins u=1..5, hand-factored
__device__ __forceinline__ void dft12_5(const float* __restrict__ v,
                                        float* __restrict__ hr,
                                        float* __restrict__ hi)
{
    const float S3 = 0.86602540378f;
    float A1 = v[1]-v[5]-v[7]+v[11];
    float B1 = v[2]-v[4]-v[8]+v[10];
    float D1 = v[0]-v[6];
    float A2 = v[1]+v[5]-v[7]-v[11];
    float B2 = v[2]+v[4]-v[8]-v[10];
    float D2 = v[3]-v[9];
    float t1 = S3*A1, t2 = 0.5f*B1;
    float s1 = 0.5f*A2, s2 = S3*B2;
    hr[0] = D1 + t1 + t2;            hi[0] = -(s1 + s2 + D2);   // u=1
    hr[4] = D1 - t1 + t2;            hi[4] = -(s1 - s2 + D2);   // u=5
    float p0 = v[0]+v[6], p3 = v[3]+v[9];
    float q1 = v[1]+v[7], q2 = v[2]+v[8], q4 = v[4]+v[10], q5 = v[5]+v[11];
    hr[1] = (p0 - p3) + 0.5f*((q1+q5) - (q2+q4));               // u=2
    hi[1] = -S3*((q1+q2) - (q4+q5));
    hr[2] = (v[0]+v[4]+v[8]) - (v[2]+v[6]+v[10]);               // u=3
    hi[2] = (v[3]+v[7]+v[11]) - (v[1]+v[5]+v[9]);
    float E0 = p0+p3, E1 = q1+q4, E2 = q2+q5;
    hr[3] = E0 - 0.5f*(E1+E2);                                  // u=4
    hi[3] = -S3*(E1-E2);
}

__device__ __forceinline__ float fast_atan2f(float y, float x) {
    float ax = fabsf(x), ay = fabsf(y);
    float mx = fmaxf(ax, ay), mn = fminf(ax, ay);
    float t = __fdividef(mn, mx);
    float s = t*t;
    float p =             -0.01172120f;
    p = fmaf(p, s,         0.05265332f);
    p = fmaf(p, s,        -0.11643287f);
    p = fmaf(p, s,         0.19354346f);
    p = fmaf(p, s,        -0.33262347f);
    p = fmaf(p, s,         0.99997726f);
    float r = p * t;
    if (ay > ax)  r = 1.57079632679f - r;
    if (x < 0.f)  r = 3.14159265359f - r;
    return copysignf(r, y);
}

// ---------------------------------------------------------------------------
// Shared memory union: wred (warp partials) aliases the front of each layout;
// all writes are ordered after the last read of the aliased region (see notes
// at call sites).
// ---------------------------------------------------------------------------
union SmemU {
    float wred[8];                        // warp partial sums
    struct {
        ulonglong2 H[5][540];             // [u][swizzled col] = {reI,imI,reO,imO}
    } stft;
    struct {
        float2 sxy[42][45];               // (x,y) pixel pairs
        float2 hA[42][33];                // (hx, hy)
        float2 hB[42][33];                // (h_{xx+yy}, h_xy)
    } ssim;
};

// deterministic 256-thread reduction: shuffle tree + 1 barrier. tid 0 holds sum.
__device__ __forceinline__ float block_reduce_256(float v, float* wbuf, int tid)
{
    #pragma unroll
    for (int o = 16; o > 0; o >>= 1)
        v += __shfl_down_sync(0xffffffffu, v, o);
    if ((tid & 31) == 0) wbuf[tid >> 5] = v;
    __syncthreads();
    float r = 0.f;
    if (tid < 32) {
        r = (tid < 8) ? wbuf[tid] : 0.f;
        #pragma unroll
        for (int o = 4; o > 0; o >>= 1)
            r += __shfl_down_sync(0xffffffffu, r, o);
    }
    return r;
}

// ---------------------------------------------------------------------------
// SSIM tile path, specialized on EDGE (16/25 tiles are interior: no bounds
// checks anywhere).
// ---------------------------------------------------------------------------
template<bool EDGE>
__device__ __forceinline__ float ssim_tile(SmemU& S,
                                           const float* __restrict__ pin,
                                           const float* __restrict__ pout,
                                           int ox, int oy, int tid)
{
    // ---- load 42x42 tile; incremental (r,cc) indexing, no division in loop ----
    {
        int r = tid / 42, cc = tid - r * 42;
        const int base = oy * 480 + ox * 3;
        #pragma unroll
        for (int j = 0; j < 7; j++) {
            if (j < 6 || tid < 228) {                    // 1764 = 6*256 + 228
                float vx = 0.f, vy = 0.f;
                if (!EDGE || ((oy + r) < 160 && (ox + cc) < 160)) {
                    int off = base + r * 480 + cc * 3;
                    vx = pin[off]; vy = pout[off];
                }
                S.ssim.sxy[r][cc] = make_float2(vx, vy);
            }
            cc += 4; r += 6;                             // += 256 elements
            if (cc >= 42) { cc -= 42; r += 1; }
        }
    }
    __syncthreads();

    // ---- horizontal pass: 42 rows x 8 groups of 4 cols, k-outer ----
    for (int i = tid; i < 42*8; i += 256) {
        int r = i >> 3, c0 = (i & 7) * 4;
        float2 A[4], Bv[4];
        #pragma unroll
        for (int g = 0; g < 4; g++) { A[g] = make_float2(0.f,0.f); Bv[g] = make_float2(0.f,0.f); }
        #pragma unroll
        for (int k = 0; k < 14; k++) {
            float2 xy = S.ssim.sxy[r][c0 + k];
            float ss = fmaf(xy.y, xy.y, xy.x*xy.x);
            float ad = xy.x * xy.y;
            #pragma unroll
            for (int g = 0; g < 4; g++) {
                const int kk = k - g;
                if (kk >= 0 && kk < 11) {
                    const float w = GNW(kk);
                    A[g].x  = fmaf(w, xy.x, A[g].x);
                    A[g].y  = fmaf(w, xy.y, A[g].y);
                    Bv[g].x = fmaf(w, ss,   Bv[g].x);
                    Bv[g].y = fmaf(w, ad,   Bv[g].y);
                }
            }
        }
        #pragma unroll
        for (int g = 0; g < 4; g++) {
            S.ssim.hA[r][c0 + g] = A[g];
            S.ssim.hB[r][c0 + g] = Bv[g];
        }
    }
    __syncthreads();

    // ---- vertical pass: 32 cols x 8 row-groups, 4 outputs/thread, k-outer ----
    const int tx = tid & 31, ty = tid >> 5;
    const int rb = ty * 4;

    float2 aA[4], aB[4];
    #pragma unroll
    for (int g = 0; g < 4; g++) { aA[g] = make_float2(0.f,0.f); aB[g] = make_float2(0.f,0.f); }

    #pragma unroll
    for (int k = 0; k < 14; k++) {
        float2 tA = S.ssim.hA[rb + k][tx];
        float2 tB = S.ssim.hB[rb + k][tx];
        #pragma unroll
        for (int g = 0; g < 4; g++) {
            const int kk = k - g;
            if (kk >= 0 && kk < 11) {
                const float w = GNW(kk);
                aA[g].x = fmaf(w, tA.x, aA[g].x);
                aA[g].y = fmaf(w, tA.y, aA[g].y);
                aB[g].x = fmaf(w, tB.x, aB[g].x);
                aB[g].y = fmaf(w, tB.y, aB[g].y);
            }
        }
    }

    float val = 0.f;
    #pragma unroll
    for (int g = 0; g < 4; g++) {
        bool ok = true;
        if (EDGE) ok = ((ox + tx) < 150) && ((oy + rb + g) < 150);
        if (ok) {
            const float C1 = 1e-4f, C2 = 9e-4f;
            float mx = aA[g].x, my = aA[g].y;
            float vsum = aB[g].x - mx*mx - my*my;        // var_x + var_y
            float cov  = aB[g].y - mx*my;
            float num = (2.f*mx*my + C1) * (2.f*cov + C2);
            float den = (mx*mx + my*my + C1) * (vsum + C2);
            val += __fdividef(num, den);                 // lum*cs, one divide
        }
    }
    return val;
}

// ---------------------------------------------------------------------------
// Fused compute kernel: bid < STFT_BLOCKS -> stft work; else ssim work.
// ---------------------------------------------------------------------------
__global__ void __launch_bounds__(256, 5) fused_kernel(const float* __restrict__ xin,
                                                       const float* __restrict__ xout)
{
    __shared__ SmemU S;
    const int tid = threadIdx.x;
    const int bid = blockIdx.x;

    if (bid < STFT_BLOCKS) {
        // =================== STFT path ===================
        const int b = bid / 38;
        const int prow = bid - b * 38;    // image rows prow*4 .. prow*4+11

        const float* pin  = xin  + ((long)b * 160 + (long)prow * 4) * 480;
        const float* pout = xout + ((long)b * 160 + (long)prow * 4) * 480;

        // Phase A: column DFTs straight from gmem (coalesced across lanes)
        for (int e = tid; e < 480; e += 256) {
            float vi[12], vo[12];
            #pragma unroll
            for (int y = 0; y < 12; y++) {
                vi[y] = pin [y*480 + e];
                vo[y] = pout[y*480 + e];
            }
            float hir[5], hii[5], hor[5], hoi[5];
            dft12_5(vi, hir, hii);
            dft12_5(vo, hor, hoi);
            const int es = e + (e >> 3);  // bank swizzle
            #pragma unroll
            for (int u = 0; u < 5; u++) {
                float4 f = make_float4(hir[u], hii[u], hor[u], hoi[u]);
                S.stft.H[u][es] = *reinterpret_cast<ulonglong2*>(&f);
            }
        }
        __syncthreads();

        // Phase B: 570 items = 38 patches x 3 ch x 5 u
        float acc = 0.f;
        for (int id = tid; id < 570; id += 256) {
            const int u = id / 114;       // 0..4  (bin u+1)
            const int m = id - u*114;     // 0..113 = j*3 + c
            const int cch = m % 3;
            const int ebase = 4*m - 3*cch;  // = 12j + c

            float Fir[5], Fii[5], For[5], Foi[5];
            #pragma unroll
            for (int v = 0; v < 5; v++) { Fir[v]=0.f; Fii[v]=0.f; For[v]=0.f; Foi[v]=0.f; }

            #pragma unroll
            for (int x = 0; x < 12; x++) {
                const int e = ebase + 3*x;
                const int es = e + (e >> 3);
                ulonglong2 hraw = S.stft.H[u][es];
                float4 h = *reinterpret_cast<float4*>(&hraw);
                #pragma unroll
                for (int v = 1; v <= 5; v++) {
                    const int k = (v*x) % 12;
                    const float c_ = cw12f(k), s_ = sw12f(k);
                    const int vi = v - 1;
                    if (s_ == 0.f) {
                        if (c_ > 0.f) { Fir[vi]+=h.x; Fii[vi]+=h.y; For[vi]+=h.z; Foi[vi]+=h.w; }
                        else          { Fir[vi]-=h.x; Fii[vi]-=h.y; For[vi]-=h.z; Foi[vi]-=h.w; }
                    } else if (c_ == 0.f) {
                        if (s_ > 0.f) { Fir[vi]+=h.y; Fii[vi]-=h.x; For[vi]+=h.w; Foi[vi]-=h.z; }
                        else          { Fir[vi]-=h.y; Fii[vi]+=h.x; For[vi]-=h.w; Foi[vi]+=h.z; }
                    } else {
                        Fir[vi] = fmaf(h.x,  c_, fmaf(h.y,  s_, Fir[vi]));
                        Fii[vi] = fmaf(h.y,  c_, fmaf(h.x, -s_, Fii[vi]));
                        For[vi] = fmaf(h.z,  c_, fmaf(h.w,  s_, For[vi]));
                        Foi[vi] = fmaf(h.w,  c_, fmaf(h.z, -s_, Foi[vi]));
                    }
                }
            }

            const float wu = (float)(u + 1) * (1.f / 25.f);
            #pragma unroll
            for (int v = 1; v <= 5; v++) {
                const int vi = v - 1;
                float angi = fast_atan2f(Fii[vi], Fir[vi] + 1e-8f);
                float ango = fast_atan2f(Foi[vi], For[vi] + 1e-8f);
                float m2i = fmaf(Fir[vi], Fir[vi], Fii[vi]*Fii[vi]);
                float m2o = fmaf(For[vi], For[vi], Foi[vi]*Foi[vi]);
                float magi = m2i * __frsqrt_rn(fmaxf(m2i, 1e-30f));
                float mago = m2o * __frsqrt_rn(fmaxf(m2o, 1e-30f));
                acc = fmaf((float)v * wu, fabsf(ango - angi) + fabsf(mago - magi), acc);
            }
        }

        __syncthreads();                  // wred aliases H: all H reads must finish
        float tot = block_reduce_256(acc, S.wred, tid);
        if (tid == 0)
            g_stft[bid] = tot;

    } else {
        // =================== SSIM path ===================
        const int idx = bid - STFT_BLOCKS;
        const int bz = idx / 25;          // b*3 + c
        const int r25 = idx - bz*25;
        const int by = r25 / 5, bx = r25 - by*5;
        const int c  = bz % 3, b = bz / 3;
        const int ox = bx * 32, oy = by * 32;

        const float* pin  = xin  + (size_t)b * (160*160*3) + c;
        const float* pout = xout + (size_t)b * (160*160*3) + c;

        // wred aliases sxy[0][0..3]; sxy's last read is in the horizontal pass,
        // which is followed by a __syncthreads inside ssim_tile -> safe.
        float val;
        if (bx < 4 && by < 4)
            val = ssim_tile<false>(S, pin, pout, ox, oy, tid);
        else
            val = ssim_tile<true >(S, pin, pout, ox, oy, tid);

        float tot = block_reduce_256(val, S.wred, tid);
        if (tid == 0)
            g_ssim[idx] = tot;
    }
}

// ---------------------------------------------------------------------------
// Final kernel: deterministic fixed-order fp64 reduction, 1024 threads,
// float4 partial loads, shuffle tree.
// loss = mean_b( -0.5*sum(1+lv-e^lv-m^2) + ssim_mean + 1e-4*stft_sum )
// ---------------------------------------------------------------------------
__global__ void __launch_bounds__(1024) final_kernel(const float* __restrict__ mean,
                                                     const float* __restrict__ logvar,
                                                     float* __restrict__ out)
{
    __shared__ double wsum[32];
    const int tid = threadIdx.x;
    double acc = 0.0;

    const double K_KLD  = -0.5 / 32.0;
    const double K_SSIM = 1.0 / (32.0 * 150.0 * 150.0 * 3.0);
    const double K_STFT = 1e-4 / 32.0;

    #pragma unroll
    for (int j = 0; j < 4; j++) {
        int i = tid + j * 1024;
        float lv = logvar[i], m = mean[i];
        acc += (double)(1.0f + lv - __expf(lv) - m*m) * K_KLD;
    }
    if (tid < 600) {                       // 2400 / 4
        float4 s = reinterpret_cast<const float4*>(g_ssim)[tid];
        acc += ((double)s.x + (double)s.y + (double)s.z + (double)s.w) * K_SSIM;
    }
    if (tid < 304) {                       // 1216 / 4
        float4 t = reinterpret_cast<const float4*>(g_stft)[tid];
        acc += ((double)t.x + (double)t.y + (double)t.z + (double)t.w) * K_STFT;
    }

    #pragma unroll
    for (int o = 16; o > 0; o >>= 1)
        acc += __shfl_down_sync(0xffffffffu, acc, o);
    if ((tid & 31) == 0) wsum[tid >> 5] = acc;
    __syncthreads();

    if (tid < 32) {
        double v = wsum[tid];
        #pragma unroll
        for (int o = 16; o > 0; o >>= 1)
            v += __shfl_down_sync(0xffffffffu, v, o);
        if (tid == 0) out[0] = (float)v;
    }
}

// ---------------------------------------------------------------------------
extern "C" void kernel_launch(void* const* d_in, const int* in_sizes, int n_in,
                              void* d_out, int out_size)
{
    const float* mean   = (const float*)d_in[0];
    const float* logvar = (const float*)d_in[1];
    const float* xin    = (const float*)d_in[2];
    const float* xout   = (const float*)d_in[3];
    float* out = (float*)d_out;

    fused_kernel<<<TOTAL_BLOCKS, 256>>>(xin, xout);
    final_kernel<<<1, 1024>>>(mean, logvar, out);
}

// round 9
// speedup vs baseline: 1.1988x; 1.0050x over previous
#include <cuda_runtime.h>
#include <math.h>

// Problem constants: B=32, N=160, C=3, L=128
// SSIM: VALID 11x11 gaussian -> 150x150 output
// STFT: f=12, s=4 -> p=38 patches/dim, bins u,v in 1..5, weight u*v/25

#define SSIM_BLOCKS (5*5*96)   // 25 tiles x (32 b * 3 c) = 2400
#define STFT_BLOCKS (38*32)    // patch rows x batch = 1216
#define TOTAL_BLOCKS (SSIM_BLOCKS + STFT_BLOCKS)

__device__ float g_ssim[SSIM_BLOCKS];
__device__ float g_stft[STFT_BLOCKS];

// gaussian weights (normalized), compile-time immediates
__device__ __forceinline__ constexpr float GNW(int k) {
    constexpr float g[11] = {0.00102838f, 0.00759887f, 0.03600077f, 0.10936069f,
                             0.21300553f, 0.26601172f, 0.21300553f, 0.10936069f,
                             0.03600077f, 0.00759887f, 0.00102838f};
    return g[k];
}

__device__ __forceinline__ constexpr float cw12f(int k) {
    constexpr float t[12] = { 1.f, 0.86602540378f, 0.5f, 0.f, -0.5f, -0.86602540378f,
                             -1.f,-0.86602540378f,-0.5f, 0.f,  0.5f,  0.86602540378f};
    return t[k];
}
__device__ __forceinline__ constexpr float sw12f(int k) {
    constexpr float t[12] = { 0.f, 0.5f, 0.86602540378f, 1.f, 0.86602540378f, 0.5f,
                              0.f,-0.5f,-0.86602540378f,-1.f,-0.86602540378f,-0.5f};
    return t[k];
}

// 12-point real-input DFT, bins u=1..5, hand-factored
__device__ __forceinline__ void dft12_5(const float* __restrict__ v,
                                        float* __restrict__ hr,
                                        float* __restrict__ hi)
{
    const float S3 = 0.86602540378f;
    float A1 = v[1]-v[5]-v[7]+v[11];
    float B1 = v[2]-v[4]-v[8]+v[10];
    float D1 = v[0]-v[6];
    float A2 = v[1]+v[5]-v[7]-v[11];
    float B2 = v[2]+v[4]-v[8]-v[10];
    float D2 = v[3]-v[9];
    float t1 = S3*A1, t2 = 0.5f*B1;
    float s1 = 0.5f*A2, s2 = S3*B2;
    hr[0] = D1 + t1 + t2;            hi[0] = -(s1 + s2 + D2);   // u=1
    hr[4] = D1 - t1 + t2;            hi[4] = -(s1 - s2 + D2);   // u=5
    float p0 = v[0]+v[6], p3 = v[3]+v[9];
    float q1 = v[1]+v[7], q2 = v[2]+v[8], q4 = v[4]+v[10], q5 = v[5]+v[11];
    hr[1] = (p0 - p3) + 0.5f*((q1+q5) - (q2+q4));               // u=2
    hi[1] = -S3*((q1+q2) - (q4+q5));
    hr[2] = (v[0]+v[4]+v[8]) - (v[2]+v[6]+v[10]);               // u=3
    hi[2] = (v[3]+v[7]+v[11]) - (v[1]+v[5]+v[9]);
    float E0 = p0+p3, E1 = q1+q4, E2 = q2+q5;
    hr[3] = E0 - 0.5f*(E1+E2);                                  // u=4
    hi[3] = -S3*(E1-E2);
}

__device__ __forceinline__ float fast_atan2f(float y, float x) {
    float ax = fabsf(x), ay = fabsf(y);
    float mx = fmaxf(ax, ay), mn = fminf(ax, ay);
    float t = __fdividef(mn, mx);
    float s = t*t;
    float p =             -0.01172120f;
    p = fmaf(p, s,         0.05265332f);
    p = fmaf(p, s,        -0.11643287f);
    p = fmaf(p, s,         0.19354346f);
    p = fmaf(p, s,        -0.33262347f);
    p = fmaf(p, s,         0.99997726f);
    float r = p * t;
    if (ay > ax)  r = 1.57079632679f - r;
    if (x < 0.f)  r = 3.14159265359f - r;
    return copysignf(r, y);
}

// ---------------------------------------------------------------------------
// Shared memory union: wred (warp partials) aliases the front of each layout;
// all writes are ordered after the last read of the aliased region.
// ---------------------------------------------------------------------------
union SmemU {
    float wred[8];                        // warp partial sums
    struct {
        ulonglong2 H[5][540];             // [u][swizzled col] = {reI,imI,reO,imO}
    } stft;
    struct {
        float2 sxy[42][45];               // (x,y) pixel pairs
        float2 hA[42][33];                // (hx, hy)
        float2 hB[42][33];                // (h_{xx+yy}, h_xy)
    } ssim;
};

// deterministic 256-thread reduction: shuffle tree + 1 barrier. tid 0 holds sum.
__device__ __forceinline__ float block_reduce_256(float v, float* wbuf, int tid)
{
    #pragma unroll
    for (int o = 16; o > 0; o >>= 1)
        v += __shfl_down_sync(0xffffffffu, v, o);
    if ((tid & 31) == 0) wbuf[tid >> 5] = v;
    __syncthreads();
    float r = 0.f;
    if (tid < 32) {
        r = (tid < 8) ? wbuf[tid] : 0.f;
        #pragma unroll
        for (int o = 4; o > 0; o >>= 1)
            r += __shfl_down_sync(0xffffffffu, r, o);
    }
    return r;
}

// ---------------------------------------------------------------------------
// SSIM tile path, specialized on EDGE (16/25 tiles are interior: no bounds
// checks anywhere).
// ---------------------------------------------------------------------------
template<bool EDGE>
__device__ __forceinline__ float ssim_tile(SmemU& S,
                                           const float* __restrict__ pin,
                                           const float* __restrict__ pout,
                                           int ox, int oy, int tid)
{
    // ---- load 42x42 tile; incremental (r,cc) indexing, no division in loop ----
    {
        int r = tid / 42, cc = tid - r * 42;
        const int base = oy * 480 + ox * 3;
        #pragma unroll
        for (int j = 0; j < 7; j++) {
            if (j < 6 || tid < 228) {                    // 1764 = 6*256 + 228
                float vx = 0.f, vy = 0.f;
                if (!EDGE || ((oy + r) < 160 && (ox + cc) < 160)) {
                    int off = base + r * 480 + cc * 3;
                    vx = pin[off]; vy = pout[off];
                }
                S.ssim.sxy[r][cc] = make_float2(vx, vy);
            }
            cc += 4; r += 6;                             // += 256 elements
            if (cc >= 42) { cc -= 42; r += 1; }
        }
    }
    __syncthreads();

    // ---- horizontal pass: 42 rows x 8 groups of 4 cols, k-outer ----
    for (int i = tid; i < 42*8; i += 256) {
        int r = i >> 3, c0 = (i & 7) * 4;
        float2 A[4], Bv[4];
        #pragma unroll
        for (int g = 0; g < 4; g++) { A[g] = make_float2(0.f,0.f); Bv[g] = make_float2(0.f,0.f); }
        #pragma unroll
        for (int k = 0; k < 14; k++) {
            float2 xy = S.ssim.sxy[r][c0 + k];
            float ss = fmaf(xy.y, xy.y, xy.x*xy.x);
            float ad = xy.x * xy.y;
            #pragma unroll
            for (int g = 0; g < 4; g++) {
                const int kk = k - g;
                if (kk >= 0 && kk < 11) {
                    const float w = GNW(kk);
                    A[g].x  = fmaf(w, xy.x, A[g].x);
                    A[g].y  = fmaf(w, xy.y, A[g].y);
                    Bv[g].x = fmaf(w, ss,   Bv[g].x);
                    Bv[g].y = fmaf(w, ad,   Bv[g].y);
                }
            }
        }
        #pragma unroll
        for (int g = 0; g < 4; g++) {
            S.ssim.hA[r][c0 + g] = A[g];
            S.ssim.hB[r][c0 + g] = Bv[g];
        }
    }
    __syncthreads();

    // ---- vertical pass: 32 cols x 8 row-groups, 4 outputs/thread, k-outer ----
    const int tx = tid & 31, ty = tid >> 5;
    const int rb = ty * 4;

    float2 aA[4], aB[4];
    #pragma unroll
    for (int g = 0; g < 4; g++) { aA[g] = make_float2(0.f,0.f); aB[g] = make_float2(0.f,0.f); }

    #pragma unroll
    for (int k = 0; k < 14; k++) {
        float2 tA = S.ssim.hA[rb + k][tx];
        float2 tB = S.ssim.hB[rb + k][tx];
        #pragma unroll
        for (int g = 0; g < 4; g++) {
            const int kk = k - g;
            if (kk >= 0 && kk < 11) {
                const float w = GNW(kk);
                aA[g].x = fmaf(w, tA.x, aA[g].x);
                aA[g].y = fmaf(w, tA.y, aA[g].y);
                aB[g].x = fmaf(w, tB.x, aB[g].x);
                aB[g].y = fmaf(w, tB.y, aB[g].y);
            }
        }
    }

    float val = 0.f;
    #pragma unroll
    for (int g = 0; g < 4; g++) {
        bool ok = true;
        if (EDGE) ok = ((ox + tx) < 150) && ((oy + rb + g) < 150);
        if (ok) {
            const float C1 = 1e-4f, C2 = 9e-4f;
            float mx = aA[g].x, my = aA[g].y;
            float vsum = aB[g].x - mx*mx - my*my;        // var_x + var_y
            float cov  = aB[g].y - mx*my;
            float num = (2.f*mx*my + C1) * (2.f*cov + C2);
            float den = (mx*mx + my*my + C1) * (vsum + C2);
            val += __fdividef(num, den);                 // lum*cs, one divide
        }
    }
    return val;
}

// ---------------------------------------------------------------------------
// Fused compute kernel: bid < STFT_BLOCKS -> stft work; else ssim work.
// ---------------------------------------------------------------------------
__global__ void __launch_bounds__(256, 5) fused_kernel(const float* __restrict__ xin,
                                                       const float* __restrict__ xout)
{
    __shared__ SmemU S;
    const int tid = threadIdx.x;
    const int bid = blockIdx.x;

    if (bid < STFT_BLOCKS) {
        // =================== STFT path ===================
        const int b = bid / 38;
        const int prow = bid - b * 38;    // image rows prow*4 .. prow*4+11

        const float* pin  = xin  + ((long)b * 160 + (long)prow * 4) * 480;
        const float* pout = xout + ((long)b * 160 + (long)prow * 4) * 480;

        // Phase A: column DFTs straight from gmem (coalesced across lanes)
        for (int e = tid; e < 480; e += 256) {
            float vi[12], vo[12];
            #pragma unroll
            for (int y = 0; y < 12; y++) {
                vi[y] = pin [y*480 + e];
                vo[y] = pout[y*480 + e];
            }
            float hir[5], hii[5], hor[5], hoi[5];
            dft12_5(vi, hir, hii);
            dft12_5(vo, hor, hoi);
            const int es = e + (e >> 3);  // bank swizzle
            #pragma unroll
            for (int u = 0; u < 5; u++) {
                float4 f = make_float4(hir[u], hii[u], hor[u], hoi[u]);
                S.stft.H[u][es] = *reinterpret_cast<ulonglong2*>(&f);
            }
        }
        __syncthreads();

        // Phase B: 570 items = 38 patches x 3 ch x 5 u
        float acc = 0.f;
        for (int id = tid; id < 570; id += 256) {
            const int u = id / 114;       // 0..4  (bin u+1)
            const int m = id - u*114;     // 0..113 = j*3 + c
            const int cch = m % 3;
            const int ebase = 4*m - 3*cch;  // = 12j + c

            float Fir[5], Fii[5], For[5], Foi[5];
            #pragma unroll
            for (int v = 0; v < 5; v++) { Fir[v]=0.f; Fii[v]=0.f; For[v]=0.f; Foi[v]=0.f; }

            #pragma unroll
            for (int x = 0; x < 12; x++) {
                const int e = ebase + 3*x;
                const int es = e + (e >> 3);
                ulonglong2 hraw = S.stft.H[u][es];
                float4 h = *reinterpret_cast<float4*>(&hraw);
                #pragma unroll
                for (int v = 1; v <= 5; v++) {
                    const int k = (v*x) % 12;
                    const float c_ = cw12f(k), s_ = sw12f(k);
                    const int vi = v - 1;
                    if (s_ == 0.f) {
                        if (c_ > 0.f) { Fir[vi]+=h.x; Fii[vi]+=h.y; For[vi]+=h.z; Foi[vi]+=h.w; }
                        else          { Fir[vi]-=h.x; Fii[vi]-=h.y; For[vi]-=h.z; Foi[vi]-=h.w; }
                    } else if (c_ == 0.f) {
                        if (s_ > 0.f) { Fir[vi]+=h.y; Fii[vi]-=h.x; For[vi]+=h.w; Foi[vi]-=h.z; }
                        else          { Fir[vi]-=h.y; Fii[vi]+=h.x; For[vi]-=h.w; Foi[vi]+=h.z; }
                    } else {
                        Fir[vi] = fmaf(h.x,  c_, fmaf(h.y,  s_, Fir[vi]));
                        Fii[vi] = fmaf(h.y,  c_, fmaf(h.x, -s_, Fii[vi]));
                        For[vi] = fmaf(h.z,  c_, fmaf(h.w,  s_, For[vi]));
                        Foi[vi] = fmaf(h.w,  c_, fmaf(h.z, -s_, Foi[vi]));
                    }
                }
            }

            const float wu = (float)(u + 1) * (1.f / 25.f);
            #pragma unroll
            for (int v = 1; v <= 5; v++) {
                const int vi = v - 1;
                float angi = fast_atan2f(Fii[vi], Fir[vi] + 1e-8f);
                float ango = fast_atan2f(Foi[vi], For[vi] + 1e-8f);
                float m2i = fmaf(Fir[vi], Fir[vi], Fii[vi]*Fii[vi]);
                float m2o = fmaf(For[vi], For[vi], Foi[vi]*Foi[vi]);
                float magi = m2i * __frsqrt_rn(fmaxf(m2i, 1e-30f));
                float mago = m2o * __frsqrt_rn(fmaxf(m2o, 1e-30f));
                acc = fmaf((float)v * wu, fabsf(ango - angi) + fabsf(mago - magi), acc);
            }
        }

        __syncthreads();                  // wred aliases H: all H reads must finish
        float tot = block_reduce_256(acc, S.wred, tid);
        if (tid == 0)
            g_stft[bid] = tot;

    } else {
        // =================== SSIM path ===================
        const int idx = bid - STFT_BLOCKS;
        const int bz = idx / 25;          // b*3 + c
        const int r25 = idx - bz*25;
        const int by = r25 / 5, bx = r25 - by*5;
        const int c  = bz % 3, b = bz / 3;
        const int ox = bx * 32, oy = by * 32;

        const float* pin  = xin  + (size_t)b * (160*160*3) + c;
        const float* pout = xout + (size_t)b * (160*160*3) + c;

        float val;
        if (bx < 4 && by < 4)
            val = ssim_tile<false>(S, pin, pout, ox, oy, tid);
        else
            val = ssim_tile<true >(S, pin, pout, ox, oy, tid);

        float tot = block_reduce_256(val, S.wred, tid);
        if (tid == 0)
            g_ssim[idx] = tot;
    }
}

// ---------------------------------------------------------------------------
// Final kernel (PDL secondary): starts WHILE fused_kernel drains. Computes the
// KLD part (depends only on kernel inputs), then cudaGridDependencySynchronize()
// waits for fused completion, then reduces the L2-hot partials.
// Deterministic fixed-order fp64 reduction.
// ---------------------------------------------------------------------------
__global__ void __launch_bounds__(1024) final_kernel(const float* __restrict__ mean,
                                                     const float* __restrict__ logvar,
                                                     float* __restrict__ out)
{
    __shared__ double wsum[32];
    const int tid = threadIdx.x;
    double acc = 0.0;

    const double K_KLD  = -0.5 / 32.0;
    const double K_SSIM = 1.0 / (32.0 * 150.0 * 150.0 * 3.0);
    const double K_STFT = 1e-4 / 32.0;

    // ---- independent prologue: overlaps with fused_kernel tail ----
    #pragma unroll
    for (int j = 0; j < 4; j++) {
        int i = tid + j * 1024;
        float lv = logvar[i], m = mean[i];
        acc += (double)(1.0f + lv - __expf(lv) - m*m) * K_KLD;
    }

    // ---- wait for fused_kernel's g_ssim/g_stft to be complete & visible ----
    cudaGridDependencySynchronize();

    if (tid < 600) {                       // 2400 / 4
        float4 s = reinterpret_cast<const float4*>(g_ssim)[tid];
        acc += ((double)s.x + (double)s.y + (double)s.z + (double)s.w) * K_SSIM;
    }
    if (tid < 304) {                       // 1216 / 4
        float4 t = reinterpret_cast<const float4*>(g_stft)[tid];
        acc += ((double)t.x + (double)t.y + (double)t.z + (double)t.w) * K_STFT;
    }

    #pragma unroll
    for (int o = 16; o > 0; o >>= 1)
        acc += __shfl_down_sync(0xffffffffu, acc, o);
    if ((tid & 31) == 0) wsum[tid >> 5] = acc;
    __syncthreads();

    if (tid < 32) {
        double v = wsum[tid];
        #pragma unroll
        for (int o = 16; o > 0; o >>= 1)
            v += __shfl_down_sync(0xffffffffu, v, o);
        if (tid == 0) out[0] = (float)v;
    }
}

// ---------------------------------------------------------------------------
extern "C" void kernel_launch(void* const* d_in, const int* in_sizes, int n_in,
                              void* d_out, int out_size)
{
    const float* mean   = (const float*)d_in[0];
    const float* logvar = (const float*)d_in[1];
    const float* xin    = (const float*)d_in[2];
    const float* xout   = (const float*)d_in[3];
    float* out = (float*)d_out;

    fused_kernel<<<TOTAL_BLOCKS, 256>>>(xin, xout);

    // PDL launch: final_kernel may begin executing while fused_kernel is still
    // running; cudaGridDependencySynchronize() inside provides the ordering.
    cudaLaunchConfig_t cfg = {};
    cfg.gridDim  = dim3(1, 1, 1);
    cfg.blockDim = dim3(1024, 1, 1);
    cfg.dynamicSmemBytes = 0;
    cfg.stream = 0;                        // same (capture) stream as above
    cudaLaunchAttribute attrs[1];
    attrs[0].id = cudaLaunchAttributeProgrammaticStreamSerialization;
    attrs[0].val.programmaticStreamSerializationAllowed = 1;
    cfg.attrs = attrs;
    cfg.numAttrs = 1;
    cudaLaunchKernelEx(&cfg, final_kernel, mean, logvar, out);
}

// round 10
// speedup vs baseline: 1.3134x; 1.0957x over previous
#include <cuda_runtime.h>
#include <math.h>

// Problem constants: B=32, N=160, C=3, L=128
// SSIM: VALID 11x11 gaussian -> 150x150 output
// STFT: f=12, s=4 -> p=38 patches/dim, bins u,v in 1..5, weight u*v/25

#define SSIM_BLOCKS (5*5*96)   // 25 tiles x (32 b * 3 c) = 2400
#define STFT_BLOCKS (38*32)    // patch rows x batch = 1216
#define TOTAL_BLOCKS (SSIM_BLOCKS + STFT_BLOCKS)

#define FXSCALE 1099511627776.0   // 2^40

// Deterministic accumulator: integer atomics commute -> same result any order.
__device__ unsigned long long g_acc = 0ULL;

// gaussian weights (normalized), compile-time immediates
__device__ __forceinline__ constexpr float GNW(int k) {
    constexpr float g[11] = {0.00102838f, 0.00759887f, 0.03600077f, 0.10936069f,
                             0.21300553f, 0.26601172f, 0.21300553f, 0.10936069f,
                             0.03600077f, 0.00759887f, 0.00102838f};
    return g[k];
}

// 12-point real-input DFT, bins 1..5, hand-factored (~55 ops)
__device__ __forceinline__ void dft12_5(const float* __restrict__ v,
                                        float* __restrict__ hr,
                                        float* __restrict__ hi)
{
    const float S3 = 0.86602540378f;
    float A1 = v[1]-v[5]-v[7]+v[11];
    float B1 = v[2]-v[4]-v[8]+v[10];
    float D1 = v[0]-v[6];
    float A2 = v[1]+v[5]-v[7]-v[11];
    float B2 = v[2]+v[4]-v[8]-v[10];
    float D2 = v[3]-v[9];
    float t1 = S3*A1, t2 = 0.5f*B1;
    float s1 = 0.5f*A2, s2 = S3*B2;
    hr[0] = D1 + t1 + t2;            hi[0] = -(s1 + s2 + D2);   // bin 1
    hr[4] = D1 - t1 + t2;            hi[4] = -(s1 - s2 + D2);   // bin 5
    float p0 = v[0]+v[6], p3 = v[3]+v[9];
    float q1 = v[1]+v[7], q2 = v[2]+v[8], q4 = v[4]+v[10], q5 = v[5]+v[11];
    hr[1] = (p0 - p3) + 0.5f*((q1+q5) - (q2+q4));               // bin 2
    hi[1] = -S3*((q1+q2) - (q4+q5));
    hr[2] = (v[0]+v[4]+v[8]) - (v[2]+v[6]+v[10]);               // bin 3
    hi[2] = (v[3]+v[7]+v[11]) - (v[1]+v[5]+v[9]);
    float E0 = p0+p3, E1 = q1+q4, E2 = q2+q5;
    hr[3] = E0 - 0.5f*(E1+E2);                                  // bin 4
    hi[3] = -S3*(E1-E2);
}

__device__ __forceinline__ float fast_atan2f(float y, float x) {
    float ax = fabsf(x), ay = fabsf(y);
    float mx = fmaxf(ax, ay), mn = fminf(ax, ay);
    float t = __fdividef(mn, mx);
    float s = t*t;
    float p =             -0.01172120f;
    p = fmaf(p, s,         0.05265332f);
    p = fmaf(p, s,        -0.11643287f);
    p = fmaf(p, s,         0.19354346f);
    p = fmaf(p, s,        -0.33262347f);
    p = fmaf(p, s,         0.99997726f);
    float r = p * t;
    if (ay > ax)  r = 1.57079632679f - r;
    if (x < 0.f)  r = 3.14159265359f - r;
    return copysignf(r, y);
}

// ---------------------------------------------------------------------------
// Shared memory union.
// ---------------------------------------------------------------------------
union SmemU {
    float wred[8];                        // warp partial sums (sync-guarded alias)
    struct {
        float2 Hin [5][512];              // [u][swizzled col] = (re, im) of x_in cols
        float2 Hout[5][512];              // ditto for x_out
    } stft;                               // 40.96 KB
    struct {
        float2 sxy[42][45];               // (x,y) pixel pairs
        float2 hA[42][33];                // (hx, hy)
        float2 hB[42][33];                // (h_{xx+yy}, h_xy)
    } ssim;                               // 37.3 KB
};

// deterministic 256-thread reduction: shuffle tree + 1 barrier. tid 0 holds sum.
__device__ __forceinline__ float block_reduce_256(float v, float* wbuf, int tid)
{
    #pragma unroll
    for (int o = 16; o > 0; o >>= 1)
        v += __shfl_down_sync(0xffffffffu, v, o);
    if ((tid & 31) == 0) wbuf[tid >> 5] = v;
    __syncthreads();
    float r = 0.f;
    if (tid < 32) {
        r = (tid < 8) ? wbuf[tid] : 0.f;
        #pragma unroll
        for (int o = 4; o > 0; o >>= 1)
            r += __shfl_down_sync(0xffffffffu, r, o);
    }
    return r;
}

// ---------------------------------------------------------------------------
// SSIM tile path, specialized on EDGE (16/25 tiles are interior).
// ---------------------------------------------------------------------------
template<bool EDGE>
__device__ __forceinline__ float ssim_tile(SmemU& S,
                                           const float* __restrict__ pin,
                                           const float* __restrict__ pout,
                                           int ox, int oy, int tid)
{
    // ---- load 42x42 tile; incremental (r,cc), no division in loop ----
    {
        int r = tid / 42, cc = tid - r * 42;
        const int base = oy * 480 + ox * 3;
        #pragma unroll
        for (int j = 0; j < 7; j++) {
            if (j < 6 || tid < 228) {                    // 1764 = 6*256 + 228
                float vx = 0.f, vy = 0.f;
                if (!EDGE || ((oy + r) < 160 && (ox + cc) < 160)) {
                    int off = base + r * 480 + cc * 3;
                    vx = pin[off]; vy = pout[off];
                }
                S.ssim.sxy[r][cc] = make_float2(vx, vy);
            }
            cc += 4; r += 6;                             // += 256 elements
            if (cc >= 42) { cc -= 42; r += 1; }
        }
    }
    __syncthreads();

    // ---- horizontal pass: 42 rows x 8 groups of 4 cols, k-outer ----
    for (int i = tid; i < 42*8; i += 256) {
        int r = i >> 3, c0 = (i & 7) * 4;
        float2 A[4], Bv[4];
        #pragma unroll
        for (int g = 0; g < 4; g++) { A[g] = make_float2(0.f,0.f); Bv[g] = make_float2(0.f,0.f); }
        #pragma unroll
        for (int k = 0; k < 14; k++) {
            float2 xy = S.ssim.sxy[r][c0 + k];
            float ss = fmaf(xy.y, xy.y, xy.x*xy.x);
            float ad = xy.x * xy.y;
            #pragma unroll
            for (int g = 0; g < 4; g++) {
                const int kk = k - g;
                if (kk >= 0 && kk < 11) {
                    const float w = GNW(kk);
                    A[g].x  = fmaf(w, xy.x, A[g].x);
                    A[g].y  = fmaf(w, xy.y, A[g].y);
                    Bv[g].x = fmaf(w, ss,   Bv[g].x);
                    Bv[g].y = fmaf(w, ad,   Bv[g].y);
                }
            }
        }
        #pragma unroll
        for (int g = 0; g < 4; g++) {
            S.ssim.hA[r][c0 + g] = A[g];
            S.ssim.hB[r][c0 + g] = Bv[g];
        }
    }
    __syncthreads();

    // ---- vertical pass: 32 cols x 8 row-groups, 4 outputs/thread, k-outer ----
    const int tx = tid & 31, ty = tid >> 5;
    const int rb = ty * 4;

    float2 aA[4], aB[4];
    #pragma unroll
    for (int g = 0; g < 4; g++) { aA[g] = make_float2(0.f,0.f); aB[g] = make_float2(0.f,0.f); }

    #pragma unroll
    for (int k = 0; k < 14; k++) {
        float2 tA = S.ssim.hA[rb + k][tx];
        float2 tB = S.ssim.hB[rb + k][tx];
        #pragma unroll
        for (int g = 0; g < 4; g++) {
            const int kk = k - g;
            if (kk >= 0 && kk < 11) {
                const float w = GNW(kk);
                aA[g].x = fmaf(w, tA.x, aA[g].x);
                aA[g].y = fmaf(w, tA.y, aA[g].y);
                aB[g].x = fmaf(w, tB.x, aB[g].x);
                aB[g].y = fmaf(w, tB.y, aB[g].y);
            }
        }
    }

    float val = 0.f;
    #pragma unroll
    for (int g = 0; g < 4; g++) {
        bool ok = true;
        if (EDGE) ok = ((ox + tx) < 150) && ((oy + rb + g) < 150);
        if (ok) {
            const float C1 = 1e-4f, C2 = 9e-4f;
            float mx = aA[g].x, my = aA[g].y;
            float vsum = aB[g].x - mx*mx - my*my;        // var_x + var_y
            float cov  = aB[g].y - mx*my;
            float num = (2.f*mx*my + C1) * (2.f*cov + C2);
            float den = (mx*mx + my*my + C1) * (vsum + C2);
            val += __fdividef(num, den);                 // lum*cs, one divide
        }
    }
    return val;
}

// ---------------------------------------------------------------------------
// Fused compute kernel: bid < STFT_BLOCKS -> stft work; else ssim work.
// Each block publishes a deterministic fixed-point partial via one atomicAdd.
// ---------------------------------------------------------------------------
__global__ void __launch_bounds__(256, 5) fused_kernel(const float* __restrict__ xin,
                                                       const float* __restrict__ xout)
{
    __shared__ SmemU S;
    const int tid = threadIdx.x;
    const int bid = blockIdx.x;

    float tot;          // block partial (valid in tid 0 after reduce)
    double K;           // weight for this block's partial

    if (bid < STFT_BLOCKS) {
        // =================== STFT path ===================
        const int b = bid / 38;
        const int prow = bid - b * 38;    // image rows prow*4 .. prow*4+11

        const float* pin  = xin  + ((long)b * 160 + (long)prow * 4) * 480;
        const float* pout = xout + ((long)b * 160 + (long)prow * 4) * 480;

        // Phase A: column DFTs straight from gmem (coalesced across lanes)
        for (int e = tid; e < 480; e += 256) {
            float vi[12], vo[12];
            #pragma unroll
            for (int y = 0; y < 12; y++) {
                vi[y] = pin [y*480 + e];
                vo[y] = pout[y*480 + e];
            }
            float hir[5], hii[5], hor[5], hoi[5];
            dft12_5(vi, hir, hii);
            dft12_5(vo, hor, hoi);
            const int es = e + (e >> 4);  // bank swizzle for float2 layout
            #pragma unroll
            for (int u = 0; u < 5; u++) {
                S.stft.Hin [u][es] = make_float2(hir[u], hii[u]);
                S.stft.Hout[u][es] = make_float2(hor[u], hoi[u]);
            }
        }
        __syncthreads();

        // Phase B: 570 items = 38 patches x 3 ch x 5 u.
        // F[v] over x is itself a 12-pt DFT of a complex sequence:
        // F = DFT(re) + i*DFT(im) -> two dft12_5 calls + combine (240 ops
        // instead of 368 naive twiddle-MACs).
        float acc = 0.f;
        for (int id = tid; id < 570; id += 256) {
            const int u = id / 114;       // 0..4  (bin u+1)
            const int m = id - u*114;     // 0..113 = j*3 + c
            const int cch = m % 3;
            const int e0 = 4*m - 3*cch;   // = 12j + c

            float Fir[5], Fii[5], For[5], Foi[5];
            {
                float ar[12], br[12];
                #pragma unroll
                for (int x = 0; x < 12; x++) {
                    int e = e0 + 3*x;
                    int es = e + (e >> 4);
                    float2 t = S.stft.Hin[u][es];
                    ar[x] = t.x; br[x] = t.y;
                }
                float Ar[5], Ai[5], Br[5], Bi[5];
                dft12_5(ar, Ar, Ai);
                dft12_5(br, Br, Bi);
                #pragma unroll
                for (int v = 0; v < 5; v++) { Fir[v] = Ar[v] - Bi[v]; Fii[v] = Ai[v] + Br[v]; }
            }
            {
                float ar[12], br[12];
                #pragma unroll
                for (int x = 0; x < 12; x++) {
                    int e = e0 + 3*x;
                    int es = e + (e >> 4);
                    float2 t = S.stft.Hout[u][es];
                    ar[x] = t.x; br[x] = t.y;
                }
                float Ar[5], Ai[5], Br[5], Bi[5];
                dft12_5(ar, Ar, Ai);
                dft12_5(br, Br, Bi);
                #pragma unroll
                for (int v = 0; v < 5; v++) { For[v] = Ar[v] - Bi[v]; Foi[v] = Ai[v] + Br[v]; }
            }

            const float wu = (float)(u + 1) * (1.f / 25.f);
            #pragma unroll
            for (int v = 1; v <= 5; v++) {
                const int vi = v - 1;
                float angi = fast_atan2f(Fii[vi], Fir[vi] + 1e-8f);
                float ango = fast_atan2f(Foi[vi], For[vi] + 1e-8f);
                float m2i = fmaf(Fir[vi], Fir[vi], Fii[vi]*Fii[vi]);
                float m2o = fmaf(For[vi], For[vi], Foi[vi]*Foi[vi]);
                float magi = m2i * __frsqrt_rn(fmaxf(m2i, 1e-30f));
                float mago = m2o * __frsqrt_rn(fmaxf(m2o, 1e-30f));
                acc = fmaf((float)v * wu, fabsf(ango - angi) + fabsf(mago - magi), acc);
            }
        }

        __syncthreads();                  // wred aliases H: all H reads must finish
        tot = block_reduce_256(acc, S.wred, tid);
        K = 1e-4 / 32.0;                  // STFT_COEF / B

    } else {
        // =================== SSIM path ===================
        const int idx = bid - STFT_BLOCKS;
        const int bz = idx / 25;          // b*3 + c
        const int r25 = idx - bz*25;
        const int by = r25 / 5, bx = r25 - by*5;
        const int c  = bz % 3, b = bz / 3;
        const int ox = bx * 32, oy = by * 32;

        const float* pin  = xin  + (size_t)b * (160*160*3) + c;
        const float* pout = xout + (size_t)b * (160*160*3) + c;

        float val;
        if (bx < 4 && by < 4)
            val = ssim_tile<false>(S, pin, pout, ox, oy, tid);
        else
            val = ssim_tile<true >(S, pin, pout, ox, oy, tid);

        tot = block_reduce_256(val, S.wred, tid);
        K = 1.0 / (32.0 * 150.0 * 150.0 * 3.0);   // ssim mean / B
    }

    // Publish: fixed-point (2^40) integer atomic -> order-independent,
    // bitwise deterministic. No fence / counter / cold epilogue.
    if (tid == 0) {
        long long q = __double2ll_rn((double)tot * K * FXSCALE);
        atomicAdd(&g_acc, (unsigned long long)q);
    }
}

// ---------------------------------------------------------------------------
// Final kernel (PDL secondary): KLD (independent of fused) computed first,
// then waits for fused and consumes g_acc (atomicExch -> read + reset for the
// next graph replay). Deterministic fixed-order fp64 reduction.
// ---------------------------------------------------------------------------
__global__ void __launch_bounds__(256) final_kernel(const float* __restrict__ mean,
                                                    const float* __restrict__ logvar,
                                                    float* __restrict__ out)
{
    __shared__ double wsum[8];
    const int tid = threadIdx.x;
    double acc = 0.0;

    const double K_KLD = -0.5 / 32.0;

    // ---- independent prologue: 4096 elems as float4 ----
    const float4* m4 = reinterpret_cast<const float4*>(mean);
    const float4* l4 = reinterpret_cast<const float4*>(logvar);
    #pragma unroll
    for (int j = 0; j < 4; j++) {
        int i = tid + j * 256;
        float4 lv = l4[i], mm = m4[i];
        float s = (1.0f + lv.x - __expf(lv.x) - mm.x*mm.x)
                + (1.0f + lv.y - __expf(lv.y) - mm.y*mm.y)
                + (1.0f + lv.z - __expf(lv.z) - mm.z*mm.z)
                + (1.0f + lv.w - __expf(lv.w) - mm.w*mm.w);
        acc += (double)s * K_KLD;
    }

    // ---- wait for fused_kernel completion & visibility ----
    cudaGridDependencySynchronize();

    if (tid == 0) {
        unsigned long long raw = atomicExch(&g_acc, 0ULL);   // consume + reset
        acc += (double)(long long)raw * (1.0 / FXSCALE);
    }

    #pragma unroll
    for (int o = 16; o > 0; o >>= 1)
        acc += __shfl_down_sync(0xffffffffu, acc, o);
    if ((tid & 31) == 0) wsum[tid >> 5] = acc;
    __syncthreads();

    if (tid < 32) {
        double v = (tid < 8) ? wsum[tid] : 0.0;
        #pragma unroll
        for (int o = 4; o > 0; o >>= 1)
            v += __shfl_down_sync(0xffffffffu, v, o);
        if (tid == 0) out[0] = (float)v;
    }
}

// ---------------------------------------------------------------------------
extern "C" void kernel_launch(void* const* d_in, const int* in_sizes, int n_in,
                              void* d_out, int out_size)
{
    const float* mean   = (const float*)d_in[0];
    const float* logvar = (const float*)d_in[1];
    const float* xin    = (const float*)d_in[2];
    const float* xout   = (const float*)d_in[3];
    float* out = (float*)d_out;

    fused_kernel<<<TOTAL_BLOCKS, 256>>>(xin, xout);

    // PDL launch: final_kernel may begin while fused_kernel drains;
    // cudaGridDependencySynchronize() inside provides the ordering.
    cudaLaunchConfig_t cfg = {};
    cfg.gridDim  = dim3(1, 1, 1);
    cfg.blockDim = dim3(256, 1, 1);
    cfg.dynamicSmemBytes = 0;
    cfg.stream = 0;
    cudaLaunchAttribute attrs[1];
    attrs[0].id = cudaLaunchAttributeProgrammaticStreamSerialization;
    attrs[0].val.programmaticStreamSerializationAllowed = 1;
    cfg.attrs = attrs;
    cfg.numAttrs = 1;
    cudaLaunchKernelEx(&cfg, final_kernel, mean, logvar, out);
}

// round 11
// speedup vs baseline: 1.3596x; 1.0351x over previous
#include <cuda_runtime.h>
#include <math.h>

// Problem constants: B=32, N=160, C=3, L=128
// SSIM: VALID 11x11 gaussian -> 150x150 output
// STFT: f=12, s=4 -> p=38 patches/dim, bins u,v in 1..5, weight u*v/25

#define SSIM_BLOCKS (5*5*96)   // 25 tiles x (32 b * 3 c) = 2400
#define STFT_BLOCKS (38*32)    // patch rows x batch = 1216
#define TOTAL_BLOCKS (SSIM_BLOCKS + STFT_BLOCKS + 1)   // +1 = KLD block (bid 0)

#define FXSCALE 1099511627776.0   // 2^40

// Deterministic accumulator: integer atomics commute -> same result any order.
__device__ unsigned long long g_acc = 0ULL;
__device__ unsigned int g_count = 0;     // completion counter (reset by last block)

// gaussian weights (normalized), compile-time immediates
__device__ __forceinline__ constexpr float GNW(int k) {
    constexpr float g[11] = {0.00102838f, 0.00759887f, 0.03600077f, 0.10936069f,
                             0.21300553f, 0.26601172f, 0.21300553f, 0.10936069f,
                             0.03600077f, 0.00759887f, 0.00102838f};
    return g[k];
}

// 12-point real-input DFT, bins 1..5, hand-factored (~55 ops)
__device__ __forceinline__ void dft12_5(const float* __restrict__ v,
                                        float* __restrict__ hr,
                                        float* __restrict__ hi)
{
    const float S3 = 0.86602540378f;
    float A1 = v[1]-v[5]-v[7]+v[11];
    float B1 = v[2]-v[4]-v[8]+v[10];
    float D1 = v[0]-v[6];
    float A2 = v[1]+v[5]-v[7]-v[11];
    float B2 = v[2]+v[4]-v[8]-v[10];
    float D2 = v[3]-v[9];
    float t1 = S3*A1, t2 = 0.5f*B1;
    float s1 = 0.5f*A2, s2 = S3*B2;
    hr[0] = D1 + t1 + t2;            hi[0] = -(s1 + s2 + D2);   // bin 1
    hr[4] = D1 - t1 + t2;            hi[4] = -(s1 - s2 + D2);   // bin 5
    float p0 = v[0]+v[6], p3 = v[3]+v[9];
    float q1 = v[1]+v[7], q2 = v[2]+v[8], q4 = v[4]+v[10], q5 = v[5]+v[11];
    hr[1] = (p0 - p3) + 0.5f*((q1+q5) - (q2+q4));               // bin 2
    hi[1] = -S3*((q1+q2) - (q4+q5));
    hr[2] = (v[0]+v[4]+v[8]) - (v[2]+v[6]+v[10]);               // bin 3
    hi[2] = (v[3]+v[7]+v[11]) - (v[1]+v[5]+v[9]);
    float E0 = p0+p3, E1 = q1+q4, E2 = q2+q5;
    hr[3] = E0 - 0.5f*(E1+E2);                                  // bin 4
    hi[3] = -S3*(E1-E2);
}

__device__ __forceinline__ float fast_atan2f(float y, float x) {
    float ax = fabsf(x), ay = fabsf(y);
    float mx = fmaxf(ax, ay), mn = fminf(ax, ay);
    float t = __fdividef(mn, mx);
    float s = t*t;
    float p =             -0.01172120f;
    p = fmaf(p, s,         0.05265332f);
    p = fmaf(p, s,        -0.11643287f);
    p = fmaf(p, s,         0.19354346f);
    p = fmaf(p, s,        -0.33262347f);
    p = fmaf(p, s,         0.99997726f);
    float r = p * t;
    if (ay > ax)  r = 1.57079632679f - r;
    if (x < 0.f)  r = 3.14159265359f - r;
    return copysignf(r, y);
}

// ---------------------------------------------------------------------------
// Shared memory union.
// ---------------------------------------------------------------------------
union SmemU {
    float  wred[8];                       // warp partial sums (sync-guarded alias)
    double dred[8];                       // fp64 warp partials (KLD block)
    struct {
        float2 Hin [5][512];              // [u][swizzled col] = (re, im) of x_in cols
        float2 Hout[5][512];              // ditto for x_out
    } stft;                               // 40.96 KB
    struct {
        float2 sxy[42][45];               // (x,y) pixel pairs
        float2 hA[42][33];                // (hx, hy)
        float2 hB[42][33];                // (h_{xx+yy}, h_xy)
    } ssim;                               // 37.3 KB
};

// deterministic 256-thread reduction: shuffle tree + 1 barrier. tid 0 holds sum.
__device__ __forceinline__ float block_reduce_256(float v, float* wbuf, int tid)
{
    #pragma unroll
    for (int o = 16; o > 0; o >>= 1)
        v += __shfl_down_sync(0xffffffffu, v, o);
    if ((tid & 31) == 0) wbuf[tid >> 5] = v;
    __syncthreads();
    float r = 0.f;
    if (tid < 32) {
        r = (tid < 8) ? wbuf[tid] : 0.f;
        #pragma unroll
        for (int o = 4; o > 0; o >>= 1)
            r += __shfl_down_sync(0xffffffffu, r, o);
    }
    return r;
}

// ---------------------------------------------------------------------------
// SSIM tile path, specialized on EDGE (16/25 tiles are interior).
// ---------------------------------------------------------------------------
template<bool EDGE>
__device__ __forceinline__ float ssim_tile(SmemU& S,
                                           const float* __restrict__ pin,
                                           const float* __restrict__ pout,
                                           int ox, int oy, int tid)
{
    // ---- load 42x42 tile; incremental (r,cc), no division in loop ----
    {
        int r = tid / 42, cc = tid - r * 42;
        const int base = oy * 480 + ox * 3;
        #pragma unroll
        for (int j = 0; j < 7; j++) {
            if (j < 6 || tid < 228) {                    // 1764 = 6*256 + 228
                float vx = 0.f, vy = 0.f;
                if (!EDGE || ((oy + r) < 160 && (ox + cc) < 160)) {
                    int off = base + r * 480 + cc * 3;
                    vx = pin[off]; vy = pout[off];
                }
                S.ssim.sxy[r][cc] = make_float2(vx, vy);
            }
            cc += 4; r += 6;                             // += 256 elements
            if (cc >= 42) { cc -= 42; r += 1; }
        }
    }
    __syncthreads();

    // ---- horizontal pass: 42 rows x 8 groups of 4 cols, k-outer ----
    for (int i = tid; i < 42*8; i += 256) {
        int r = i >> 3, c0 = (i & 7) * 4;
        float2 A[4], Bv[4];
        #pragma unroll
        for (int g = 0; g < 4; g++) { A[g] = make_float2(0.f,0.f); Bv[g] = make_float2(0.f,0.f); }
        #pragma unroll
        for (int k = 0; k < 14; k++) {
            float2 xy = S.ssim.sxy[r][c0 + k];
            float ss = fmaf(xy.y, xy.y, xy.x*xy.x);
            float ad = xy.x * xy.y;
            #pragma unroll
            for (int g = 0; g < 4; g++) {
                const int kk = k - g;
                if (kk >= 0 && kk < 11) {
                    const float w = GNW(kk);
                    A[g].x  = fmaf(w, xy.x, A[g].x);
                    A[g].y  = fmaf(w, xy.y, A[g].y);
                    Bv[g].x = fmaf(w, ss,   Bv[g].x);
                    Bv[g].y = fmaf(w, ad,   Bv[g].y);
                }
            }
        }
        #pragma unroll
        for (int g = 0; g < 4; g++) {
            S.ssim.hA[r][c0 + g] = A[g];
            S.ssim.hB[r][c0 + g] = Bv[g];
        }
    }
    __syncthreads();

    // ---- vertical pass: 32 cols x 8 row-groups, 4 outputs/thread, k-outer ----
    const int tx = tid & 31, ty = tid >> 5;
    const int rb = ty * 4;

    float2 aA[4], aB[4];
    #pragma unroll
    for (int g = 0; g < 4; g++) { aA[g] = make_float2(0.f,0.f); aB[g] = make_float2(0.f,0.f); }

    #pragma unroll
    for (int k = 0; k < 14; k++) {
        float2 tA = S.ssim.hA[rb + k][tx];
        float2 tB = S.ssim.hB[rb + k][tx];
        #pragma unroll
        for (int g = 0; g < 4; g++) {
            const int kk = k - g;
            if (kk >= 0 && kk < 11) {
                const float w = GNW(kk);
                aA[g].x = fmaf(w, tA.x, aA[g].x);
                aA[g].y = fmaf(w, tA.y, aA[g].y);
                aB[g].x = fmaf(w, tB.x, aB[g].x);
                aB[g].y = fmaf(w, tB.y, aB[g].y);
            }
        }
    }

    float val = 0.f;
    #pragma unroll
    for (int g = 0; g < 4; g++) {
        bool ok = true;
        if (EDGE) ok = ((ox + tx) < 150) && ((oy + rb + g) < 150);
        if (ok) {
            const float C1 = 1e-4f, C2 = 9e-4f;
            float mx = aA[g].x, my = aA[g].y;
            float vsum = aB[g].x - mx*mx - my*my;        // var_x + var_y
            float cov  = aB[g].y - mx*my;
            float num = (2.f*mx*my + C1) * (2.f*cov + C2);
            float den = (mx*mx + my*my + C1) * (vsum + C2);
            val += __fdividef(num, den);                 // lum*cs, one divide
        }
    }
    return val;
}

// ---------------------------------------------------------------------------
// Single fused kernel: bid 0 -> KLD; bid 1..STFT_BLOCKS -> stft; rest -> ssim.
// Every block publishes a deterministic fixed-point partial (one atomicAdd);
// the LAST block to finish converts g_acc and writes out (then resets state
// for the next graph replay).
// ---------------------------------------------------------------------------
__global__ void __launch_bounds__(256, 5) fused_kernel(const float* __restrict__ xin,
                                                       const float* __restrict__ xout,
                                                       const float* __restrict__ mean,
                                                       const float* __restrict__ logvar,
                                                       float* __restrict__ out)
{
    __shared__ SmemU S;
    const int tid = threadIdx.x;
    const int bid = blockIdx.x;

    long long q = 0;     // this block's fixed-point partial (valid in tid 0)

    if (bid == 0) {
        // =================== KLD block ===================
        const double K_KLD = -0.5 / 32.0;
        const float4* m4 = reinterpret_cast<const float4*>(mean);
        const float4* l4 = reinterpret_cast<const float4*>(logvar);
        double acc = 0.0;
        #pragma unroll
        for (int j = 0; j < 4; j++) {
            int i = tid + j * 256;
            float4 lv = l4[i], mm = m4[i];
            float s = (1.0f + lv.x - __expf(lv.x) - mm.x*mm.x)
                    + (1.0f + lv.y - __expf(lv.y) - mm.y*mm.y)
                    + (1.0f + lv.z - __expf(lv.z) - mm.z*mm.z)
                    + (1.0f + lv.w - __expf(lv.w) - mm.w*mm.w);
            acc += (double)s * K_KLD;
        }
        #pragma unroll
        for (int o = 16; o > 0; o >>= 1)
            acc += __shfl_down_sync(0xffffffffu, acc, o);
        if ((tid & 31) == 0) S.dred[tid >> 5] = acc;
        __syncthreads();
        if (tid < 32) {
            double v = (tid < 8) ? S.dred[tid] : 0.0;
            #pragma unroll
            for (int o = 4; o > 0; o >>= 1)
                v += __shfl_down_sync(0xffffffffu, v, o);
            if (tid == 0) q = __double2ll_rn(v * FXSCALE);
        }

    } else if (bid <= STFT_BLOCKS) {
        // =================== STFT path ===================
        const int sbid = bid - 1;
        const int b = sbid / 38;
        const int prow = sbid - b * 38;   // image rows prow*4 .. prow*4+11

        const float* pin  = xin  + ((long)b * 160 + (long)prow * 4) * 480;
        const float* pout = xout + ((long)b * 160 + (long)prow * 4) * 480;

        // Phase A: column DFTs straight from gmem (coalesced across lanes)
        for (int e = tid; e < 480; e += 256) {
            float vi[12], vo[12];
            #pragma unroll
            for (int y = 0; y < 12; y++) {
                vi[y] = pin [y*480 + e];
                vo[y] = pout[y*480 + e];
            }
            float hir[5], hii[5], hor[5], hoi[5];
            dft12_5(vi, hir, hii);
            dft12_5(vo, hor, hoi);
            const int es = e + (e >> 4);  // bank swizzle for float2 layout
            #pragma unroll
            for (int u = 0; u < 5; u++) {
                S.stft.Hin [u][es] = make_float2(hir[u], hii[u]);
                S.stft.Hout[u][es] = make_float2(hor[u], hoi[u]);
            }
        }
        __syncthreads();

        // Phase B: 570 items = 38 patches x 3 ch x 5 u.
        // F = DFT(re) + i*DFT(im) via two hand-factored real DFTs.
        float acc = 0.f;
        for (int id = tid; id < 570; id += 256) {
            const int u = id / 114;       // 0..4  (bin u+1)
            const int m = id - u*114;     // 0..113 = j*3 + c
            const int cch = m % 3;
            const int e0 = 4*m - 3*cch;   // = 12j + c

            float Fir[5], Fii[5], For[5], Foi[5];
            {
                float ar[12], br[12];
                #pragma unroll
                for (int x = 0; x < 12; x++) {
                    int e = e0 + 3*x;
                    int es = e + (e >> 4);
                    float2 t = S.stft.Hin[u][es];
                    ar[x] = t.x; br[x] = t.y;
                }
                float Ar[5], Ai[5], Br[5], Bi[5];
                dft12_5(ar, Ar, Ai);
                dft12_5(br, Br, Bi);
                #pragma unroll
                for (int v = 0; v < 5; v++) { Fir[v] = Ar[v] - Bi[v]; Fii[v] = Ai[v] + Br[v]; }
            }
            {
                float ar[12], br[12];
                #pragma unroll
                for (int x = 0; x < 12; x++) {
                    int e = e0 + 3*x;
                    int es = e + (e >> 4);
                    float2 t = S.stft.Hout[u][es];
                    ar[x] = t.x; br[x] = t.y;
                }
                float Ar[5], Ai[5], Br[5], Bi[5];
                dft12_5(ar, Ar, Ai);
                dft12_5(br, Br, Bi);
                #pragma unroll
                for (int v = 0; v < 5; v++) { For[v] = Ar[v] - Bi[v]; Foi[v] = Ai[v] + Br[v]; }
            }

            const float wu = (float)(u + 1) * (1.f / 25.f);
            #pragma unroll
            for (int v = 1; v <= 5; v++) {
                const int vi = v - 1;
                float angi = fast_atan2f(Fii[vi], Fir[vi] + 1e-8f);
                float ango = fast_atan2f(Foi[vi], For[vi] + 1e-8f);
                float m2i = fmaf(Fir[vi], Fir[vi], Fii[vi]*Fii[vi]);
                float m2o = fmaf(For[vi], For[vi], Foi[vi]*Foi[vi]);
                float magi = m2i * __frsqrt_rn(fmaxf(m2i, 1e-30f));
                float mago = m2o * __frsqrt_rn(fmaxf(m2o, 1e-30f));
                acc = fmaf((float)v * wu, fabsf(ango - angi) + fabsf(mago - magi), acc);
            }
        }

        __syncthreads();                  // wred aliases H: all H reads must finish
        float tot = block_reduce_256(acc, S.wred, tid);
        if (tid == 0)
            q = __double2ll_rn((double)tot * (1e-4 / 32.0) * FXSCALE);

    } else {
        // =================== SSIM path ===================
        const int idx = bid - 1 - STFT_BLOCKS;
        const int bz = idx / 25;          // b*3 + c
        const int r25 = idx - bz*25;
        const int by = r25 / 5, bx = r25 - by*5;
        const int c  = bz % 3, b = bz / 3;
        const int ox = bx * 32, oy = by * 32;

        const float* pin  = xin  + (size_t)b * (160*160*3) + c;
        const float* pout = xout + (size_t)b * (160*160*3) + c;

        float val;
        if (bx < 4 && by < 4)
            val = ssim_tile<false>(S, pin, pout, ox, oy, tid);
        else
            val = ssim_tile<true >(S, pin, pout, ox, oy, tid);

        float tot = block_reduce_256(val, S.wred, tid);
        if (tid == 0)
            q = __double2ll_rn((double)tot * (1.0 / (32.0 * 150.0 * 150.0 * 3.0)) * FXSCALE);
    }

    // ---- publish + last-block finalize (tid 0 only; ~8 instructions) ----
    if (tid == 0) {
        atomicAdd(&g_acc, (unsigned long long)q);
        __threadfence();                  // order g_acc add before counter add
        unsigned int old = atomicAdd(&g_count, 1u);
        if (old == TOTAL_BLOCKS - 1) {    // I'm the last block
            unsigned long long raw = atomicExch(&g_acc, 0ULL);  // consume + reset
            out[0] = (float)((double)(long long)raw * (1.0 / FXSCALE));
            g_count = 0;                  // reset for next graph replay
        }
    }
}

// ---------------------------------------------------------------------------
extern "C" void kernel_launch(void* const* d_in, const int* in_sizes, int n_in,
                              void* d_out, int out_size)
{
    const float* mean   = (const float*)d_in[0];
    const float* logvar = (const float*)d_in[1];
    const float* xin    = (const float*)d_in[2];
    const float* xout   = (const float*)d_in[3];
    float* out = (float*)d_out;

    fused_kernel<<<TOTAL_BLOCKS, 256>>>(xin, xout, mean, logvar, out);
}

// round 12
// speedup vs baseline: 1.4383x; 1.0579x over previous
#include <cuda_runtime.h>
#include <math.h>

// Problem constants: B=32, N=160, C=3, L=128
// SSIM: VALID 11x11 gaussian -> 150x150 output
// STFT: f=12, s=4 -> p=38 patches/dim, bins u,v in 1..5, weight u*v/25

#define SSIM_BLOCKS (5*5*96)   // 25 tiles x (32 b * 3 c) = 2400
#define STFT_BLOCKS (38*32)    // patch rows x batch = 1216
#define TOTAL_BLOCKS (SSIM_BLOCKS + STFT_BLOCKS + 1)   // +1 = KLD block (bid 0)

#define FXSCALE 1099511627776.0   // 2^40

// Deterministic accumulator: integer atomics commute -> same result any order.
__device__ unsigned long long g_acc = 0ULL;
__device__ unsigned int g_count = 0;     // completion counter (reset by last block)

// gaussian weights (normalized), compile-time immediates
__device__ __forceinline__ constexpr float GNW(int k) {
    constexpr float g[11] = {0.00102838f, 0.00759887f, 0.03600077f, 0.10936069f,
                             0.21300553f, 0.26601172f, 0.21300553f, 0.10936069f,
                             0.03600077f, 0.00759887f, 0.00102838f};
    return g[k];
}

// 12-point real-input DFT, bins 1..5, hand-factored (~55 ops)
__device__ __forceinline__ void dft12_5(const float* __restrict__ v,
                                        float* __restrict__ hr,
                                        float* __restrict__ hi)
{
    const float S3 = 0.86602540378f;
    float A1 = v[1]-v[5]-v[7]+v[11];
    float B1 = v[2]-v[4]-v[8]+v[10];
    float D1 = v[0]-v[6];
    float A2 = v[1]+v[5]-v[7]-v[11];
    float B2 = v[2]+v[4]-v[8]-v[10];
    float D2 = v[3]-v[9];
    float t1 = S3*A1, t2 = 0.5f*B1;
    float s1 = 0.5f*A2, s2 = S3*B2;
    hr[0] = D1 + t1 + t2;            hi[0] = -(s1 + s2 + D2);   // bin 1
    hr[4] = D1 - t1 + t2;            hi[4] = -(s1 - s2 + D2);   // bin 5
    float p0 = v[0]+v[6], p3 = v[3]+v[9];
    float q1 = v[1]+v[7], q2 = v[2]+v[8], q4 = v[4]+v[10], q5 = v[5]+v[11];
    hr[1] = (p0 - p3) + 0.5f*((q1+q5) - (q2+q4));               // bin 2
    hi[1] = -S3*((q1+q2) - (q4+q5));
    hr[2] = (v[0]+v[4]+v[8]) - (v[2]+v[6]+v[10]);               // bin 3
    hi[2] = (v[3]+v[7]+v[11]) - (v[1]+v[5]+v[9]);
    float E0 = p0+p3, E1 = q1+q4, E2 = q2+q5;
    hr[3] = E0 - 0.5f*(E1+E2);                                  // bin 4
    hi[3] = -S3*(E1-E2);
}

// atan2, 5-term minimax (A&S 4.4.49, |err| <= 1e-5 rad)
__device__ __forceinline__ float fast_atan2f(float y, float x) {
    float ax = fabsf(x), ay = fabsf(y);
    float mx = fmaxf(ax, ay), mn = fminf(ax, ay);
    float t = __fdividef(mn, mx);
    float s = t*t;
    float p =              0.0208351f;
    p = fmaf(p, s,        -0.0851330f);
    p = fmaf(p, s,         0.1801410f);
    p = fmaf(p, s,        -0.3302995f);
    p = fmaf(p, s,         0.9998660f);
    float r = p * t;
    if (ay > ax)  r = 1.57079632679f - r;
    if (x < 0.f)  r = 3.14159265359f - r;
    return copysignf(r, y);
}

// ---------------------------------------------------------------------------
// Shared memory union.
// stft: NO swizzle -> phase-B loads are affine (LDS with immediate offsets,
// zero address ALU). Pad 482 so the u-row stride isn't 0 mod 32 banks.
// Worst bank conflict N=2 (verified lane-by-lane), crossbar non-binding.
// ssim: hA/hB merged into float4 (LDS.128/STS.128); horizontal pass iterates
// row-major (r = i%42) so store banks 4r mod 32 are all distinct.
// ---------------------------------------------------------------------------
union SmemU {
    float  wred[8];                       // warp partial sums (sync-guarded alias)
    double dred[8];                       // fp64 warp partials (KLD block)
    struct {
        float2 Hin [5][482];              // [u][col] = (re, im) of x_in columns
        float2 Hout[5][482];              // ditto for x_out
    } stft;                               // 38.56 KB
    struct {
        float2 sxy[42][45];               // (x,y) pixel pairs
        float4 hAB[42][33];               // (hx, hy, h_{xx+yy}, h_xy)
    } ssim;                               // 37.3 KB
};

// deterministic 256-thread reduction: shuffle tree + 1 barrier. tid 0 holds sum.
__device__ __forceinline__ float block_reduce_256(float v, float* wbuf, int tid)
{
    #pragma unroll
    for (int o = 16; o > 0; o >>= 1)
        v += __shfl_down_sync(0xffffffffu, v, o);
    if ((tid & 31) == 0) wbuf[tid >> 5] = v;
    __syncthreads();
    float r = 0.f;
    if (tid < 32) {
        r = (tid < 8) ? wbuf[tid] : 0.f;
        #pragma unroll
        for (int o = 4; o > 0; o >>= 1)
            r += __shfl_down_sync(0xffffffffu, r, o);
    }
    return r;
}

// ---------------------------------------------------------------------------
// SSIM tile path, specialized on EDGE (16/25 tiles are interior).
// ---------------------------------------------------------------------------
template<bool EDGE>
__device__ __forceinline__ float ssim_tile(SmemU& S,
                                           const float* __restrict__ pin,
                                           const float* __restrict__ pout,
                                           int ox, int oy, int tid)
{
    // ---- load 42x42 tile; incremental (r,cc), no division in loop ----
    {
        int r = tid / 42, cc = tid - r * 42;
        const int base = oy * 480 + ox * 3;
        #pragma unroll
        for (int j = 0; j < 7; j++) {
            if (j < 6 || tid < 228) {                    // 1764 = 6*256 + 228
                float vx = 0.f, vy = 0.f;
                if (!EDGE || ((oy + r) < 160 && (ox + cc) < 160)) {
                    int off = base + r * 480 + cc * 3;
                    vx = pin[off]; vy = pout[off];
                }
                S.ssim.sxy[r][cc] = make_float2(vx, vy);
            }
            cc += 4; r += 6;                             // += 256 elements
            if (cc >= 42) { cc -= 42; r += 1; }
        }
    }
    __syncthreads();

    // ---- horizontal pass: row-major mapping (r = i % 42) so the 4 STS.128
    //      per thread hit distinct banks across lanes (4r mod 32 distinct). ----
    for (int i = tid; i < 42*8; i += 256) {
        int grp = i / 42;                 // 0..7
        int r   = i - grp * 42;           // 0..41
        int c0  = grp * 4;
        float2 A[4], Bv[4];
        #pragma unroll
        for (int g = 0; g < 4; g++) { A[g] = make_float2(0.f,0.f); Bv[g] = make_float2(0.f,0.f); }
        #pragma unroll
        for (int k = 0; k < 14; k++) {
            float2 xy = S.ssim.sxy[r][c0 + k];
            float ss = fmaf(xy.y, xy.y, xy.x*xy.x);
            float ad = xy.x * xy.y;
            #pragma unroll
            for (int g = 0; g < 4; g++) {
                const int kk = k - g;
                if (kk >= 0 && kk < 11) {
                    const float w = GNW(kk);
                    A[g].x  = fmaf(w, xy.x, A[g].x);
                    A[g].y  = fmaf(w, xy.y, A[g].y);
                    Bv[g].x = fmaf(w, ss,   Bv[g].x);
                    Bv[g].y = fmaf(w, ad,   Bv[g].y);
                }
            }
        }
        #pragma unroll
        for (int g = 0; g < 4; g++)
            S.ssim.hAB[r][c0 + g] = make_float4(A[g].x, A[g].y, Bv[g].x, Bv[g].y);
    }
    __syncthreads();

    // ---- vertical pass: 32 cols x 8 row-groups, 4 outputs/thread, k-outer.
    //      hAB reads are lane-consecutive float4 -> conflict-free LDS.128. ----
    const int tx = tid & 31, ty = tid >> 5;
    const int rb = ty * 4;

    float2 aA[4], aB[4];
    #pragma unroll
    for (int g = 0; g < 4; g++) { aA[g] = make_float2(0.f,0.f); aB[g] = make_float2(0.f,0.f); }

    #pragma unroll
    for (int k = 0; k < 14; k++) {
        float4 t = S.ssim.hAB[rb + k][tx];
        #pragma unroll
        for (int g = 0; g < 4; g++) {
            const int kk = k - g;
            if (kk >= 0 && kk < 11) {
                const float w = GNW(kk);
                aA[g].x = fmaf(w, t.x, aA[g].x);
                aA[g].y = fmaf(w, t.y, aA[g].y);
                aB[g].x = fmaf(w, t.z, aB[g].x);
                aB[g].y = fmaf(w, t.w, aB[g].y);
            }
        }
    }

    float val = 0.f;
    #pragma unroll
    for (int g = 0; g < 4; g++) {
        bool ok = true;
        if (EDGE) ok = ((ox + tx) < 150) && ((oy + rb + g) < 150);
        if (ok) {
            const float C1 = 1e-4f, C2 = 9e-4f;
            float mx = aA[g].x, my = aA[g].y;
            float vsum = aB[g].x - mx*mx - my*my;        // var_x + var_y
            float cov  = aB[g].y - mx*my;
            float num = (2.f*mx*my + C1) * (2.f*cov + C2);
            float den = (mx*mx + my*my + C1) * (vsum + C2);
            val += __fdividef(num, den);                 // lum*cs, one divide
        }
    }
    return val;
}

// ---------------------------------------------------------------------------
// Single fused kernel: bid 0 -> KLD; bid 1..STFT_BLOCKS -> stft; rest -> ssim.
// Every block publishes a deterministic fixed-point partial (one atomicAdd);
// the LAST block converts g_acc, writes out, resets state for graph replay.
// ---------------------------------------------------------------------------
__global__ void __launch_bounds__(256, 5) fused_kernel(const float* __restrict__ xin,
                                                       const float* __restrict__ xout,
                                                       const float* __restrict__ mean,
                                                       const float* __restrict__ logvar,
                                                       float* __restrict__ out)
{
    __shared__ SmemU S;
    const int tid = threadIdx.x;
    const int bid = blockIdx.x;

    long long q = 0;     // this block's fixed-point partial (valid in tid 0)

    if (bid == 0) {
        // =================== KLD block ===================
        const double K_KLD = -0.5 / 32.0;
        const float4* m4 = reinterpret_cast<const float4*>(mean);
        const float4* l4 = reinterpret_cast<const float4*>(logvar);
        double acc = 0.0;
        #pragma unroll
        for (int j = 0; j < 4; j++) {
            int i = tid + j * 256;
            float4 lv = l4[i], mm = m4[i];
            float s = (1.0f + lv.x - __expf(lv.x) - mm.x*mm.x)
                    + (1.0f + lv.y - __expf(lv.y) - mm.y*mm.y)
                    + (1.0f + lv.z - __expf(lv.z) - mm.z*mm.z)
                    + (1.0f + lv.w - __expf(lv.w) - mm.w*mm.w);
            acc += (double)s * K_KLD;
        }
        #pragma unroll
        for (int o = 16; o > 0; o >>= 1)
            acc += __shfl_down_sync(0xffffffffu, acc, o);
        if ((tid & 31) == 0) S.dred[tid >> 5] = acc;
        __syncthreads();
        if (tid < 32) {
            double v = (tid < 8) ? S.dred[tid] : 0.0;
            #pragma unroll
            for (int o = 4; o > 0; o >>= 1)
                v += __shfl_down_sync(0xffffffffu, v, o);
            if (tid == 0) q = __double2ll_rn(v * FXSCALE);
        }

    } else if (bid <= STFT_BLOCKS) {
        // =================== STFT path ===================
        const int sbid = bid - 1;
        const int b = sbid / 38;
        const int prow = sbid - b * 38;   // image rows prow*4 .. prow*4+11

        const float* pin  = xin  + ((long)b * 160 + (long)prow * 4) * 480;
        const float* pout = xout + ((long)b * 160 + (long)prow * 4) * 480;

        // Phase A: column DFTs straight from gmem (coalesced across lanes);
        // direct (unswizzled) stores, conflict-free.
        for (int e = tid; e < 480; e += 256) {
            float vi[12], vo[12];
            #pragma unroll
            for (int y = 0; y < 12; y++) {
                vi[y] = pin [y*480 + e];
                vo[y] = pout[y*480 + e];
            }
            float hir[5], hii[5], hor[5], hoi[5];
            dft12_5(vi, hir, hii);
            dft12_5(vo, hor, hoi);
            #pragma unroll
            for (int u = 0; u < 5; u++) {
                S.stft.Hin [u][e] = make_float2(hir[u], hii[u]);
                S.stft.Hout[u][e] = make_float2(hor[u], hoi[u]);
            }
        }
        __syncthreads();

        // Phase B: 570 items = 38 patches x 3 ch x 5 u.
        // F = DFT(re) + i*DFT(im). Loads are base + 24x bytes (affine!) ->
        // immediate-offset LDS, zero per-load address ALU.
        float acc = 0.f;
        for (int id = tid; id < 570; id += 256) {
            const int u = id / 114;       // 0..4  (bin u+1)
            const int m = id - u*114;     // 0..113 = j*3 + c
            const int cch = m % 3;
            const int e0 = 4*m - 3*cch;   // = 12j + c

            float Fir[5], Fii[5], For[5], Foi[5];
            {
                const float2* __restrict__ p = &S.stft.Hin[u][e0];
                float ar[12], br[12];
                #pragma unroll
                for (int x = 0; x < 12; x++) {
                    float2 t = p[3*x];
                    ar[x] = t.x; br[x] = t.y;
                }
                float Ar[5], Ai[5], Br[5], Bi[5];
                dft12_5(ar, Ar, Ai);
                dft12_5(br, Br, Bi);
                #pragma unroll
                for (int v = 0; v < 5; v++) { Fir[v] = Ar[v] - Bi[v]; Fii[v] = Ai[v] + Br[v]; }
            }
            {
                const float2* __restrict__ p = &S.stft.Hout[u][e0];
                float ar[12], br[12];
                #pragma unroll
                for (int x = 0; x < 12; x++) {
                    float2 t = p[3*x];
                    ar[x] = t.x; br[x] = t.y;
                }
                float Ar[5], Ai[5], Br[5], Bi[5];
                dft12_5(ar, Ar, Ai);
                dft12_5(br, Br, Bi);
                #pragma unroll
                for (int v = 0; v < 5; v++) { For[v] = Ar[v] - Bi[v]; Foi[v] = Ai[v] + Br[v]; }
            }

            const float wu = (float)(u + 1) * (1.f / 25.f);
            #pragma unroll
            for (int v = 1; v <= 5; v++) {
                const int vi = v - 1;
                float angi = fast_atan2f(Fii[vi], Fir[vi] + 1e-8f);
                float ango = fast_atan2f(Foi[vi], For[vi] + 1e-8f);
                float m2i = fmaf(Fir[vi], Fir[vi], Fii[vi]*Fii[vi]);
                float m2o = fmaf(For[vi], For[vi], Foi[vi]*Foi[vi]);
                float magi = m2i * __frsqrt_rn(fmaxf(m2i, 1e-30f));
                float mago = m2o * __frsqrt_rn(fmaxf(m2o, 1e-30f));
                acc = fmaf((float)v * wu, fabsf(ango - angi) + fabsf(mago - magi), acc);
            }
        }

        __syncthreads();                  // wred aliases H: all H reads must finish
        float tot = block_reduce_256(acc, S.wred, tid);
        if (tid == 0)
            q = __double2ll_rn((double)tot * (1e-4 / 32.0) * FXSCALE);

    } else {
        // =================== SSIM path ===================
        const int idx = bid - 1 - STFT_BLOCKS;
        const int bz = idx / 25;          // b*3 + c
        const int r25 = idx - bz*25;
        const int by = r25 / 5, bx = r25 - by*5;
        const int c  = bz % 3, b = bz / 3;
        const int ox = bx * 32, oy = by * 32;

        const float* pin  = xin  + (size_t)b * (160*160*3) + c;
        const float* pout = xout + (size_t)b * (160*160*3) + c;

        float val;
        if (bx < 4 && by < 4)
            val = ssim_tile<false>(S, pin, pout, ox, oy, tid);
        else
            val = ssim_tile<true >(S, pin, pout, ox, oy, tid);

        float tot = block_reduce_256(val, S.wred, tid);
        if (tid == 0)
            q = __double2ll_rn((double)tot * (1.0 / (32.0 * 150.0 * 150.0 * 3.0)) * FXSCALE);
    }

    // ---- publish + last-block finalize (tid 0 only) ----
    if (tid == 0) {
        atomicAdd(&g_acc, (unsigned long long)q);
        __threadfence();                  // order g_acc add before counter add
        unsigned int old = atomicAdd(&g_count, 1u);
        if (old == TOTAL_BLOCKS - 1) {    // I'm the last block
            unsigned long long raw = atomicExch(&g_acc, 0ULL);  // consume + reset
            out[0] = (float)((double)(long long)raw * (1.0 / FXSCALE));
            g_count = 0;                  // reset for next graph replay
        }
    }
}

// ---------------------------------------------------------------------------
extern "C" void kernel_launch(void* const* d_in, const int* in_sizes, int n_in,
                              void* d_out, int out_size)
{
    const float* mean   = (const float*)d_in[0];
    const float* logvar = (const float*)d_in[1];
    const float* xin    = (const float*)d_in[2];
    const float* xout   = (const float*)d_in[3];
    float* out = (float*)d_out;

    fused_kernel<<<TOTAL_BLOCKS, 256>>>(xin, xout, mean, logvar, out);
}

// round 13
// speedup vs baseline: 1.4858x; 1.0330x over previous
#include <cuda_runtime.h>
#include <math.h>

// Problem constants: B=32, N=160, C=3, L=128
// SSIM: VALID 11x11 gaussian -> 150x150 output
// STFT: f=12, s=4 -> p=38 patches/dim, bins u,v in 1..5, weight u*v/25

#define SSIM_BLOCKS (5*5*96)   // 25 tiles x (32 b * 3 c) = 2400
#define STFT_BLOCKS (38*32)    // patch rows x batch = 1216
#define TOTAL_BLOCKS (SSIM_BLOCKS + STFT_BLOCKS + 1)   // +1 = KLD block (bid 0)

#define FXSCALE 1099511627776.0   // 2^40

// Deterministic accumulator: integer atomics commute -> same result any order.
__device__ unsigned long long g_acc = 0ULL;
__device__ unsigned int g_count = 0;     // completion counter (reset by last block)

typedef unsigned long long ull;

// ---- packed f32x2 primitives (register-pair aligned operands only!) ----
#define FMA2(d, a, b, c) asm("fma.rn.f32x2 %0, %1, %2, %3;" : "=l"(d) : "l"(a), "l"(b), "l"(c))
#define MUL2(d, a, b)    asm("mul.rn.f32x2 %0, %1, %2;"     : "=l"(d) : "l"(a), "l"(b))
#define ADD2(d, a, b)    asm("add.rn.f32x2 %0, %1, %2;"     : "=l"(d) : "l"(a), "l"(b))
#define SUB2(d, a, b)    asm("sub.rn.f32x2 %0, %1, %2;"     : "=l"(d) : "l"(a), "l"(b))

__device__ __forceinline__ ull pk(float lo, float hi) {
    ull r; asm("mov.b64 %0, {%1, %2};" : "=l"(r) : "f"(lo), "f"(hi)); return r;
}
__device__ __forceinline__ float2 up2(ull v) {
    float2 r; asm("mov.b64 {%0, %1}, %2;" : "=f"(r.x), "=f"(r.y) : "l"(v)); return r;
}

// gaussian weights (normalized), compile-time immediates
__device__ __forceinline__ constexpr float GNW(int k) {
    constexpr float g[11] = {0.00102838f, 0.00759887f, 0.03600077f, 0.10936069f,
                             0.21300553f, 0.26601172f, 0.21300553f, 0.10936069f,
                             0.03600077f, 0.00759887f, 0.00102838f};
    return g[k];
}

// 12-point real-input DFT, bins 1..5, hand-factored, SCALAR (phase A)
__device__ __forceinline__ void dft12_5(const float* __restrict__ v,
                                        float* __restrict__ hr,
                                        float* __restrict__ hi)
{
    const float S3 = 0.86602540378f;
    float A1 = v[1]-v[5]-v[7]+v[11];
    float B1 = v[2]-v[4]-v[8]+v[10];
    float D1 = v[0]-v[6];
    float A2 = v[1]+v[5]-v[7]-v[11];
    float B2 = v[2]+v[4]-v[8]-v[10];
    float D2 = v[3]-v[9];
    float t1 = S3*A1, t2 = 0.5f*B1;
    float s1 = 0.5f*A2, s2 = S3*B2;
    hr[0] = D1 + t1 + t2;            hi[0] = -(s1 + s2 + D2);   // bin 1
    hr[4] = D1 - t1 + t2;            hi[4] = -(s1 - s2 + D2);   // bin 5
    float p0 = v[0]+v[6], p3 = v[3]+v[9];
    float q1 = v[1]+v[7], q2 = v[2]+v[8], q4 = v[4]+v[10], q5 = v[5]+v[11];
    hr[1] = (p0 - p3) + 0.5f*((q1+q5) - (q2+q4));               // bin 2
    hi[1] = -S3*((q1+q2) - (q4+q5));
    hr[2] = (v[0]+v[4]+v[8]) - (v[2]+v[6]+v[10]);               // bin 3
    hi[2] = (v[3]+v[7]+v[11]) - (v[1]+v[5]+v[9]);
    float E0 = p0+p3, E1 = q1+q4, E2 = q2+q5;
    hr[3] = E0 - 0.5f*(E1+E2);                                  // bin 4
    hi[3] = -S3*(E1-E2);
}

// PACKED 12-point DFT, bins 1..5, both f32 lanes independently.
// Outputs: hr[v] = sum v*cos  (per lane), g[v] = sum v*sin (per lane) = -hi.
__device__ __forceinline__ void dft12_5_p(const ull* __restrict__ v,
                                          ull* __restrict__ hr,
                                          ull* __restrict__ g,
                                          ull p05, ull m05, ull pS3)
{
    ull A1, B1, D1, A2, B2, D2, t1, t2, s1, s2, t, a, b;
    SUB2(A1, v[1], v[5]);  SUB2(A1, A1, v[7]);  ADD2(A1, A1, v[11]);
    SUB2(B1, v[2], v[4]);  SUB2(B1, B1, v[8]);  ADD2(B1, B1, v[10]);
    SUB2(D1, v[0], v[6]);
    ADD2(A2, v[1], v[5]);  SUB2(A2, A2, v[7]);  SUB2(A2, A2, v[11]);
    ADD2(B2, v[2], v[4]);  SUB2(B2, B2, v[8]);  SUB2(B2, B2, v[10]);
    SUB2(D2, v[3], v[9]);
    MUL2(t1, pS3, A1);  MUL2(t2, p05, B1);
    MUL2(s1, p05, A2);  MUL2(s2, pS3, B2);
    // bins 1, 5
    ADD2(t, t1, t2);  ADD2(hr[0], D1, t);
    ADD2(t, s1, s2);  ADD2(g[0], t, D2);          // g = +(s1+s2+D2)
    SUB2(t, t2, t1);  ADD2(hr[4], D1, t);
    SUB2(t, s1, s2);  ADD2(g[4], t, D2);
    // even bins
    ull p0, p3, q1, q2, q4, q5;
    ADD2(p0, v[0], v[6]);  ADD2(p3, v[3], v[9]);
    ADD2(q1, v[1], v[7]);  ADD2(q2, v[2], v[8]);
    ADD2(q4, v[4], v[10]); ADD2(q5, v[5], v[11]);
    ADD2(a, q1, q5);  ADD2(b, q2, q4);  SUB2(a, a, b);
    SUB2(t, p0, p3);  FMA2(hr[1], p05, a, t);
    ADD2(a, q1, q2);  ADD2(b, q4, q5);  SUB2(a, a, b);  MUL2(g[1], pS3, a);
    ADD2(a, v[0], v[4]);  ADD2(a, a, v[8]);
    ADD2(b, v[2], v[6]);  ADD2(b, b, v[10]);  SUB2(hr[2], a, b);
    ADD2(a, v[1], v[5]);  ADD2(a, a, v[9]);
    ADD2(b, v[3], v[7]);  ADD2(b, b, v[11]); SUB2(g[2], a, b);   // g2 = -(hi2)
    ull E0, E1, E2;
    ADD2(E0, p0, p3);  ADD2(E1, q1, q4);  ADD2(E2, q2, q5);
    ADD2(t, E1, E2);   FMA2(hr[3], m05, t, E0);
    SUB2(t, E1, E2);   MUL2(g[3], pS3, t);
}

// atan2, 5-term minimax (A&S 4.4.49, |err| <= 1e-5 rad)
__device__ __forceinline__ float fast_atan2f(float y, float x) {
    float ax = fabsf(x), ay = fabsf(y);
    float mx = fmaxf(ax, ay), mn = fminf(ax, ay);
    float t = __fdividef(mn, mx);
    float s = t*t;
    float p =              0.0208351f;
    p = fmaf(p, s,        -0.0851330f);
    p = fmaf(p, s,         0.1801410f);
    p = fmaf(p, s,        -0.3302995f);
    p = fmaf(p, s,         0.9998660f);
    float r = p * t;
    if (ay > ax)  r = 1.57079632679f - r;
    if (x < 0.f)  r = 3.14159265359f - r;
    return copysignf(r, y);
}

// ---------------------------------------------------------------------------
// Shared memory union (layouts identical to R12; packing is arithmetic-only).
// ---------------------------------------------------------------------------
union SmemU {
    float  wred[8];                       // warp partial sums (sync-guarded alias)
    double dred[8];                       // fp64 warp partials (KLD block)
    struct {
        float2 Hin [5][482];              // [u][col] = (re, im) of x_in columns
        float2 Hout[5][482];              // ditto for x_out
    } stft;                               // 38.56 KB
    struct {
        float2 sxy[42][45];               // (x,y) pixel pairs
        float4 hAB[42][33];               // (hx, hy, h_{xx+yy}, h_xy)
    } ssim;                               // 37.3 KB
};

// deterministic 256-thread reduction: shuffle tree + 1 barrier. tid 0 holds sum.
__device__ __forceinline__ float block_reduce_256(float v, float* wbuf, int tid)
{
    #pragma unroll
    for (int o = 16; o > 0; o >>= 1)
        v += __shfl_down_sync(0xffffffffu, v, o);
    if ((tid & 31) == 0) wbuf[tid >> 5] = v;
    __syncthreads();
    float r = 0.f;
    if (tid < 32) {
        r = (tid < 8) ? wbuf[tid] : 0.f;
        #pragma unroll
        for (int o = 4; o > 0; o >>= 1)
            r += __shfl_down_sync(0xffffffffu, r, o);
    }
    return r;
}

// ---------------------------------------------------------------------------
// SSIM tile path, specialized on EDGE; packed f32x2 accumulators.
// ---------------------------------------------------------------------------
template<bool EDGE>
__device__ __forceinline__ float ssim_tile(SmemU& S,
                                           const float* __restrict__ pin,
                                           const float* __restrict__ pout,
                                           int ox, int oy, int tid)
{
    // packed gaussian weights (6 distinct, symmetric)
    ull ww[6];
    #pragma unroll
    for (int k = 0; k < 6; k++) ww[k] = pk(GNW(k), GNW(k));

    // ---- load 42x42 tile; incremental (r,cc), no division in loop ----
    {
        int r = tid / 42, cc = tid - r * 42;
        const int base = oy * 480 + ox * 3;
        #pragma unroll
        for (int j = 0; j < 7; j++) {
            if (j < 6 || tid < 228) {                    // 1764 = 6*256 + 228
                float vx = 0.f, vy = 0.f;
                if (!EDGE || ((oy + r) < 160 && (ox + cc) < 160)) {
                    int off = base + r * 480 + cc * 3;
                    vx = pin[off]; vy = pout[off];
                }
                S.ssim.sxy[r][cc] = make_float2(vx, vy);
            }
            cc += 4; r += 6;                             // += 256 elements
            if (cc >= 42) { cc -= 42; r += 1; }
        }
    }
    __syncthreads();

    // ---- horizontal pass: row-major mapping (r = i % 42); packed FMA2 ----
    for (int i = tid; i < 42*8; i += 256) {
        int grp = i / 42;                 // 0..7
        int r   = i - grp * 42;           // 0..41
        int c0  = grp * 4;
        ull A[4] = {0,0,0,0}, Bv[4] = {0,0,0,0};
        #pragma unroll
        for (int k = 0; k < 14; k++) {
            ull xy = *reinterpret_cast<const ull*>(&S.ssim.sxy[r][c0 + k]);
            float2 f = up2(xy);
            float ss = fmaf(f.y, f.y, f.x*f.x);
            float ad = f.x * f.y;
            ull ssad = pk(ss, ad);
            #pragma unroll
            for (int g = 0; g < 4; g++) {
                const int kk = k - g;
                if (kk >= 0 && kk < 11) {
                    const int wi = (kk <= 5) ? kk : 10 - kk;
                    FMA2(A[g],  ww[wi], xy,   A[g]);
                    FMA2(Bv[g], ww[wi], ssad, Bv[g]);
                }
            }
        }
        #pragma unroll
        for (int g = 0; g < 4; g++)
            *reinterpret_cast<ulonglong2*>(&S.ssim.hAB[r][c0 + g]) =
                make_ulonglong2(A[g], Bv[g]);
    }
    __syncthreads();

    // ---- vertical pass: 32 cols x 8 row-groups, 4 outputs/thread; FMA2 ----
    const int tx = tid & 31, ty = tid >> 5;
    const int rb = ty * 4;

    ull aA[4] = {0,0,0,0}, aB[4] = {0,0,0,0};

    #pragma unroll
    for (int k = 0; k < 14; k++) {
        ulonglong2 t = *reinterpret_cast<const ulonglong2*>(&S.ssim.hAB[rb + k][tx]);
        #pragma unroll
        for (int g = 0; g < 4; g++) {
            const int kk = k - g;
            if (kk >= 0 && kk < 11) {
                const int wi = (kk <= 5) ? kk : 10 - kk;
                FMA2(aA[g], ww[wi], t.x, aA[g]);
                FMA2(aB[g], ww[wi], t.y, aB[g]);
            }
        }
    }

    float val = 0.f;
    #pragma unroll
    for (int g = 0; g < 4; g++) {
        bool ok = true;
        if (EDGE) ok = ((ox + tx) < 150) && ((oy + rb + g) < 150);
        if (ok) {
            const float C1 = 1e-4f, C2 = 9e-4f;
            float2 m01 = up2(aA[g]);      // (mx, my)
            float2 e01 = up2(aB[g]);      // (e_{xx+yy}, e_xy)
            float mx = m01.x, my = m01.y;
            float vsum = e01.x - mx*mx - my*my;          // var_x + var_y
            float cov  = e01.y - mx*my;
            float num = (2.f*mx*my + C1) * (2.f*cov + C2);
            float den = (mx*mx + my*my + C1) * (vsum + C2);
            val += __fdividef(num, den);                 // lum*cs, one divide
        }
    }
    return val;
}

// ---------------------------------------------------------------------------
// Single fused kernel: bid 0 -> KLD; bid 1..STFT_BLOCKS -> stft; rest -> ssim.
// ---------------------------------------------------------------------------
__global__ void __launch_bounds__(256, 5) fused_kernel(const float* __restrict__ xin,
                                                       const float* __restrict__ xout,
                                                       const float* __restrict__ mean,
                                                       const float* __restrict__ logvar,
                                                       float* __restrict__ out)
{
    __shared__ SmemU S;
    const int tid = threadIdx.x;
    const int bid = blockIdx.x;

    long long q = 0;     // this block's fixed-point partial (valid in tid 0)

    if (bid == 0) {
        // =================== KLD block ===================
        const double K_KLD = -0.5 / 32.0;
        const float4* m4 = reinterpret_cast<const float4*>(mean);
        const float4* l4 = reinterpret_cast<const float4*>(logvar);
        double acc = 0.0;
        #pragma unroll
        for (int j = 0; j < 4; j++) {
            int i = tid + j * 256;
            float4 lv = l4[i], mm = m4[i];
            float s = (1.0f + lv.x - __expf(lv.x) - mm.x*mm.x)
                    + (1.0f + lv.y - __expf(lv.y) - mm.y*mm.y)
                    + (1.0f + lv.z - __expf(lv.z) - mm.z*mm.z)
                    + (1.0f + lv.w - __expf(lv.w) - mm.w*mm.w);
            acc += (double)s * K_KLD;
        }
        #pragma unroll
        for (int o = 16; o > 0; o >>= 1)
            acc += __shfl_down_sync(0xffffffffu, acc, o);
        if ((tid & 31) == 0) S.dred[tid >> 5] = acc;
        __syncthreads();
        if (tid < 32) {
            double v = (tid < 8) ? S.dred[tid] : 0.0;
            #pragma unroll
            for (int o = 4; o > 0; o >>= 1)
                v += __shfl_down_sync(0xffffffffu, v, o);
            if (tid == 0) q = __double2ll_rn(v * FXSCALE);
        }

    } else if (bid <= STFT_BLOCKS) {
        // =================== STFT path ===================
        const int sbid = bid - 1;
        const int b = sbid / 38;
        const int prow = sbid - b * 38;   // image rows prow*4 .. prow*4+11

        const float* pin  = xin  + ((long)b * 160 + (long)prow * 4) * 480;
        const float* pout = xout + ((long)b * 160 + (long)prow * 4) * 480;

        const ull p05 = pk(0.5f, 0.5f);
        const ull m05 = pk(-0.5f, -0.5f);
        const ull pS3 = pk(0.86602540378f, 0.86602540378f);

        // Phase A: scalar column DFTs straight from gmem (coalesced)
        for (int e = tid; e < 480; e += 256) {
            float vi[12], vo[12];
            #pragma unroll
            for (int y = 0; y < 12; y++) {
                vi[y] = pin [y*480 + e];
                vo[y] = pout[y*480 + e];
            }
            float hir[5], hii[5], hor[5], hoi[5];
            dft12_5(vi, hir, hii);
            dft12_5(vo, hor, hoi);
            #pragma unroll
            for (int u = 0; u < 5; u++) {
                S.stft.Hin [u][e] = make_float2(hir[u], hii[u]);
                S.stft.Hout[u][e] = make_float2(hor[u], hoi[u]);
            }
        }
        __syncthreads();

        // Phase B: 570 items. The (re,im) float2 in smem IS the packed f32x2
        // operand: ONE packed DFT per image replaces two scalar DFTs.
        // Combine (lane-crossing, register halves): F.re = P.x - Q.y = P.x + G.y
        // is wrong sign-wise; with G = +sum*sin = -Q:  F.re = P.x - Q.y = P.x + G.y?
        // Careful: Q = -G. F.re = P.x - Q.y = P.x + G.y. F.im = P.y + Q.x = P.y - G.x.
        float acc = 0.f;
        for (int id = tid; id < 570; id += 256) {
            const int u = id / 114;       // 0..4  (bin u+1)
            const int m = id - u*114;     // 0..113 = j*3 + c
            const int cch = m % 3;
            const int e0 = 4*m - 3*cch;   // = 12j + c

            float Fir[5], Fii[5], For[5], Foi[5];
            {
                ull c[12];
                #pragma unroll
                for (int x = 0; x < 12; x++)
                    c[x] = *reinterpret_cast<const ull*>(&S.stft.Hin[u][e0 + 3*x]);
                ull P[5], G[5];
                dft12_5_p(c, P, G, p05, m05, pS3);
                #pragma unroll
                for (int v = 0; v < 5; v++) {
                    float2 pv = up2(P[v]), gv = up2(G[v]);
                    Fir[v] = pv.x + gv.y;
                    Fii[v] = pv.y - gv.x;
                }
            }
            {
                ull c[12];
                #pragma unroll
                for (int x = 0; x < 12; x++)
                    c[x] = *reinterpret_cast<const ull*>(&S.stft.Hout[u][e0 + 3*x]);
                ull P[5], G[5];
                dft12_5_p(c, P, G, p05, m05, pS3);
                #pragma unroll
                for (int v = 0; v < 5; v++) {
                    float2 pv = up2(P[v]), gv = up2(G[v]);
                    For[v] = pv.x + gv.y;
                    Foi[v] = pv.y - gv.x;
                }
            }

            const float wu = (float)(u + 1) * (1.f / 25.f);
            #pragma unroll
            for (int v = 1; v <= 5; v++) {
                const int vi = v - 1;
                float angi = fast_atan2f(Fii[vi], Fir[vi] + 1e-8f);
                float ango = fast_atan2f(Foi[vi], For[vi] + 1e-8f);
                float m2i = fmaf(Fir[vi], Fir[vi], Fii[vi]*Fii[vi]);
                float m2o = fmaf(For[vi], For[vi], Foi[vi]*Foi[vi]);
                float magi = m2i * __frsqrt_rn(fmaxf(m2i, 1e-30f));
                float mago = m2o * __frsqrt_rn(fmaxf(m2o, 1e-30f));
                acc = fmaf((float)v * wu, fabsf(ango - angi) + fabsf(mago - magi), acc);
            }
        }

        __syncthreads();                  // wred aliases H: all H reads must finish
        float tot = block_reduce_256(acc, S.wred, tid);
        if (tid == 0)
            q = __double2ll_rn((double)tot * (1e-4 / 32.0) * FXSCALE);

    } else {
        // =================== SSIM path ===================
        const int idx = bid - 1 - STFT_BLOCKS;
        const int bz = idx / 25;          // b*3 + c
        const int r25 = idx - bz*25;
        const int by = r25 / 5, bx = r25 - by*5;
        const int c  = bz % 3, b = bz / 3;
        const int ox = bx * 32, oy = by * 32;

        const float* pin  = xin  + (size_t)b * (160*160*3) + c;
        const float* pout = xout + (size_t)b * (160*160*3) + c;

        float val;
        if (bx < 4 && by < 4)
            val = ssim_tile<false>(S, pin, pout, ox, oy, tid);
        else
            val = ssim_tile<true >(S, pin, pout, ox, oy, tid);

        float tot = block_reduce_256(val, S.wred, tid);
        if (tid == 0)
            q = __double2ll_rn((double)tot * (1.0 / (32.0 * 150.0 * 150.0 * 3.0)) * FXSCALE);
    }

    // ---- publish + last-block finalize (tid 0 only) ----
    if (tid == 0) {
        atomicAdd(&g_acc, (unsigned long long)q);
        __threadfence();                  // order g_acc add before counter add
        unsigned int old = atomicAdd(&g_count, 1u);
        if (old == TOTAL_BLOCKS - 1) {    // I'm the last block
            unsigned long long raw = atomicExch(&g_acc, 0ULL);  // consume + reset
            out[0] = (float)((double)(long long)raw * (1.0 / FXSCALE));
            g_count = 0;                  // reset for next graph replay
        }
    }
}

// ---------------------------------------------------------------------------
extern "C" void kernel_launch(void* const* d_in, const int* in_sizes, int n_in,
                              void* d_out, int out_size)
{
    const float* mean   = (const float*)d_in[0];
    const float* logvar = (const float*)d_in[1];
    const float* xin    = (const float*)d_in[2];
    const float* xout   = (const float*)d_in[3];
    float* out = (float*)d_out;

    fused_kernel<<<TOTAL_BLOCKS, 256>>>(xin, xout, mean, logvar, out);
}

// round 14
// speedup vs baseline: 1.5714x; 1.0576x over previous
#include <cuda_runtime.h>
#include <math.h>

// Problem constants: B=32, N=160, C=3, L=128
// SSIM: VALID 11x11 gaussian -> 150x150 output
// STFT: f=12, s=4 -> p=38 patches/dim, bins u,v in 1..5, weight u*v/25

#define SSIM_BLOCKS (5*5*96)   // 25 tiles x (32 b * 3 c) = 2400
#define STFT_BLOCKS (38*32)    // patch rows x batch = 1216
#define TOTAL_BLOCKS (SSIM_BLOCKS + STFT_BLOCKS + 1)   // +1 = KLD block (bid 0)

#define FXSCALE 1099511627776.0   // 2^40

// Deterministic accumulator: integer atomics commute -> same result any order.
__device__ unsigned long long g_acc = 0ULL;
__device__ unsigned int g_count = 0;     // completion counter (reset by last block)

typedef unsigned long long ull;

// ---- packed f32x2 primitives. RF-banking note: only 2-source forms (ADD2/
// SUB2/MUL2, rt=2 for 2 lanes) are a true 2x; FMA2 (3 pairs -> rt=3) is used
// sparingly. Scalar FFMA with an immediate multiplier (rt=1) is preferred for
// weight convolutions. ----
#define FMA2(d, a, b, c) asm("fma.rn.f32x2 %0, %1, %2, %3;" : "=l"(d) : "l"(a), "l"(b), "l"(c))
#define MUL2(d, a, b)    asm("mul.rn.f32x2 %0, %1, %2;"     : "=l"(d) : "l"(a), "l"(b))
#define ADD2(d, a, b)    asm("add.rn.f32x2 %0, %1, %2;"     : "=l"(d) : "l"(a), "l"(b))
#define SUB2(d, a, b)    asm("sub.rn.f32x2 %0, %1, %2;"     : "=l"(d) : "l"(a), "l"(b))

__device__ __forceinline__ ull pk(float lo, float hi) {
    ull r; asm("mov.b64 %0, {%1, %2};" : "=l"(r) : "f"(lo), "f"(hi)); return r;
}
__device__ __forceinline__ float2 up2(ull v) {
    float2 r; asm("mov.b64 {%0, %1}, %2;" : "=f"(r.x), "=f"(r.y) : "l"(v)); return r;
}
__device__ __forceinline__ float fsqrt_approx(float x) {
    float r; asm("sqrt.approx.f32 %0, %1;" : "=f"(r) : "f"(x)); return r;
}

// gaussian weights (normalized), compile-time immediates
__device__ __forceinline__ constexpr float GNW(int k) {
    constexpr float g[11] = {0.00102838f, 0.00759887f, 0.03600077f, 0.10936069f,
                             0.21300553f, 0.26601172f, 0.21300553f, 0.10936069f,
                             0.03600077f, 0.00759887f, 0.00102838f};
    return g[k];
}

// PACKED 12-point DFT, bins 1..5, both f32 lanes independently.
// Outputs: hr[v] = sum·cos (per lane), g[v] = sum·sin (per lane) (= -im).
__device__ __forceinline__ void dft12_5_p(const ull* __restrict__ v,
                                          ull* __restrict__ hr,
                                          ull* __restrict__ g,
                                          ull p05, ull m05, ull pS3)
{
    ull A1, B1, D1, A2, B2, D2, t1, t2, s1, s2, t, a, b;
    SUB2(A1, v[1], v[5]);  SUB2(A1, A1, v[7]);  ADD2(A1, A1, v[11]);
    SUB2(B1, v[2], v[4]);  SUB2(B1, B1, v[8]);  ADD2(B1, B1, v[10]);
    SUB2(D1, v[0], v[6]);
    ADD2(A2, v[1], v[5]);  SUB2(A2, A2, v[7]);  SUB2(A2, A2, v[11]);
    ADD2(B2, v[2], v[4]);  SUB2(B2, B2, v[8]);  SUB2(B2, B2, v[10]);
    SUB2(D2, v[3], v[9]);
    MUL2(t1, pS3, A1);  MUL2(t2, p05, B1);
    MUL2(s1, p05, A2);  MUL2(s2, pS3, B2);
    // bins 1, 5
    ADD2(t, t1, t2);  ADD2(hr[0], D1, t);
    ADD2(t, s1, s2);  ADD2(g[0], t, D2);
    SUB2(t, t2, t1);  ADD2(hr[4], D1, t);
    SUB2(t, s1, s2);  ADD2(g[4], t, D2);
    // even bins
    ull p0, p3, q1, q2, q4, q5;
    ADD2(p0, v[0], v[6]);  ADD2(p3, v[3], v[9]);
    ADD2(q1, v[1], v[7]);  ADD2(q2, v[2], v[8]);
    ADD2(q4, v[4], v[10]); ADD2(q5, v[5], v[11]);
    ADD2(a, q1, q5);  ADD2(b, q2, q4);  SUB2(a, a, b);
    SUB2(t, p0, p3);  FMA2(hr[1], p05, a, t);
    ADD2(a, q1, q2);  ADD2(b, q4, q5);  SUB2(a, a, b);  MUL2(g[1], pS3, a);
    ADD2(a, v[0], v[4]);  ADD2(a, a, v[8]);
    ADD2(b, v[2], v[6]);  ADD2(b, b, v[10]);  SUB2(hr[2], a, b);
    ADD2(a, v[1], v[5]);  ADD2(a, a, v[9]);
    ADD2(b, v[3], v[7]);  ADD2(b, b, v[11]); SUB2(g[2], a, b);
    ull E0, E1, E2;
    ADD2(E0, p0, p3);  ADD2(E1, q1, q4);  ADD2(E2, q2, q5);
    ADD2(t, E1, E2);   FMA2(hr[3], m05, t, E0);
    SUB2(t, E1, E2);   MUL2(g[3], pS3, t);
}

// atan2, 5-term minimax (A&S 4.4.49, |err| <= 1e-5 rad)
__device__ __forceinline__ float fast_atan2f(float y, float x) {
    float ax = fabsf(x), ay = fabsf(y);
    float mx = fmaxf(ax, ay), mn = fminf(ax, ay);
    float t = __fdividef(mn, mx);
    float s = t*t;
    float p =              0.0208351f;
    p = fmaf(p, s,        -0.0851330f);
    p = fmaf(p, s,         0.1801410f);
    p = fmaf(p, s,        -0.3302995f);
    p = fmaf(p, s,         0.9998660f);
    float r = p * t;
    if (ay > ax)  r = 1.57079632679f - r;
    if (x < 0.f)  r = 3.14159265359f - r;
    return copysignf(r, y);
}

// ---------------------------------------------------------------------------
// Shared memory union. stft H stores (re, +g) per image (g = sin-sum = -im);
// affine phase-B addressing (no swizzle; pad 482; worst conflict N=2).
// ---------------------------------------------------------------------------
union SmemU {
    float  wred[8];                       // warp partial sums (sync-guarded alias)
    double dred[8];                       // fp64 warp partials (KLD block)
    struct {
        float2 Hin [5][482];              // [u][col] = (re, g) of x_in columns
        float2 Hout[5][482];              // ditto for x_out
    } stft;                               // 38.56 KB
    struct {
        float2 sxy[42][45];               // (x,y) pixel pairs
        float4 hAB[42][33];               // (hx, hy, h_{xx+yy}, h_xy)
    } ssim;                               // 37.3 KB
};

// deterministic 256-thread reduction: shuffle tree + 1 barrier. tid 0 holds sum.
__device__ __forceinline__ float block_reduce_256(float v, float* wbuf, int tid)
{
    #pragma unroll
    for (int o = 16; o > 0; o >>= 1)
        v += __shfl_down_sync(0xffffffffu, v, o);
    if ((tid & 31) == 0) wbuf[tid >> 5] = v;
    __syncthreads();
    float r = 0.f;
    if (tid < 32) {
        r = (tid < 8) ? wbuf[tid] : 0.f;
        #pragma unroll
        for (int o = 4; o > 0; o >>= 1)
            r += __shfl_down_sync(0xffffffffu, r, o);
    }
    return r;
}

// ---------------------------------------------------------------------------
// SSIM tile path (SCALAR FFMA-imm convolutions: rt=1 beats FMA2's rt=3).
// ---------------------------------------------------------------------------
template<bool EDGE>
__device__ __forceinline__ float ssim_tile(SmemU& S,
                                           const float* __restrict__ pin,
                                           const float* __restrict__ pout,
                                           int ox, int oy, int tid)
{
    // ---- load 42x42 tile; incremental (r,cc), no division in loop ----
    {
        int r = tid / 42, cc = tid - r * 42;
        const int base = oy * 480 + ox * 3;
        #pragma unroll
        for (int j = 0; j < 7; j++) {
            if (j < 6 || tid < 228) {                    // 1764 = 6*256 + 228
                float vx = 0.f, vy = 0.f;
                if (!EDGE || ((oy + r) < 160 && (ox + cc) < 160)) {
                    int off = base + r * 480 + cc * 3;
                    vx = pin[off]; vy = pout[off];
                }
                S.ssim.sxy[r][cc] = make_float2(vx, vy);
            }
            cc += 4; r += 6;                             // += 256 elements
            if (cc >= 42) { cc -= 42; r += 1; }
        }
    }
    __syncthreads();

    // ---- horizontal pass: row-major mapping (r = i % 42); scalar FFMA-imm ----
    for (int i = tid; i < 42*8; i += 256) {
        int grp = i / 42;                 // 0..7
        int r   = i - grp * 42;           // 0..41
        int c0  = grp * 4;
        float2 A[4], Bv[4];
        #pragma unroll
        for (int g = 0; g < 4; g++) { A[g] = make_float2(0.f,0.f); Bv[g] = make_float2(0.f,0.f); }
        #pragma unroll
        for (int k = 0; k < 14; k++) {
            float2 xy = S.ssim.sxy[r][c0 + k];
            float ss = fmaf(xy.y, xy.y, xy.x*xy.x);
            float ad = xy.x * xy.y;
            #pragma unroll
            for (int g = 0; g < 4; g++) {
                const int kk = k - g;
                if (kk >= 0 && kk < 11) {
                    const float w = GNW(kk);
                    A[g].x  = fmaf(w, xy.x, A[g].x);
                    A[g].y  = fmaf(w, xy.y, A[g].y);
                    Bv[g].x = fmaf(w, ss,   Bv[g].x);
                    Bv[g].y = fmaf(w, ad,   Bv[g].y);
                }
            }
        }
        #pragma unroll
        for (int g = 0; g < 4; g++)
            S.ssim.hAB[r][c0 + g] = make_float4(A[g].x, A[g].y, Bv[g].x, Bv[g].y);
    }
    __syncthreads();

    // ---- vertical pass: 32 cols x 8 row-groups, 4 outputs/thread; FFMA-imm ----
    const int tx = tid & 31, ty = tid >> 5;
    const int rb = ty * 4;

    float2 aA[4], aB[4];
    #pragma unroll
    for (int g = 0; g < 4; g++) { aA[g] = make_float2(0.f,0.f); aB[g] = make_float2(0.f,0.f); }

    #pragma unroll
    for (int k = 0; k < 14; k++) {
        float4 t = S.ssim.hAB[rb + k][tx];
        #pragma unroll
        for (int g = 0; g < 4; g++) {
            const int kk = k - g;
            if (kk >= 0 && kk < 11) {
                const float w = GNW(kk);
                aA[g].x = fmaf(w, t.x, aA[g].x);
                aA[g].y = fmaf(w, t.y, aA[g].y);
                aB[g].x = fmaf(w, t.z, aB[g].x);
                aB[g].y = fmaf(w, t.w, aB[g].y);
            }
        }
    }

    float val = 0.f;
    #pragma unroll
    for (int g = 0; g < 4; g++) {
        bool ok = true;
        if (EDGE) ok = ((ox + tx) < 150) && ((oy + rb + g) < 150);
        if (ok) {
            const float C1 = 1e-4f, C2 = 9e-4f;
            float mx = aA[g].x, my = aA[g].y;
            float vsum = aB[g].x - mx*mx - my*my;        // var_x + var_y
            float cov  = aB[g].y - mx*my;
            float num = (2.f*mx*my + C1) * (2.f*cov + C2);
            float den = (mx*mx + my*my + C1) * (vsum + C2);
            val += __fdividef(num, den);                 // lum*cs, one divide
        }
    }
    return val;
}

// ---------------------------------------------------------------------------
// Single fused kernel: bid 0 -> KLD; bid 1..STFT_BLOCKS -> stft; rest -> ssim.
// ---------------------------------------------------------------------------
__global__ void __launch_bounds__(256, 5) fused_kernel(const float* __restrict__ xin,
                                                       const float* __restrict__ xout,
                                                       const float* __restrict__ mean,
                                                       const float* __restrict__ logvar,
                                                       float* __restrict__ out)
{
    __shared__ SmemU S;
    const int tid = threadIdx.x;
    const int bid = blockIdx.x;

    long long q = 0;     // this block's fixed-point partial (valid in tid 0)

    if (bid == 0) {
        // =================== KLD block ===================
        const double K_KLD = -0.5 / 32.0;
        const float4* m4 = reinterpret_cast<const float4*>(mean);
        const float4* l4 = reinterpret_cast<const float4*>(logvar);
        double acc = 0.0;
        #pragma unroll
        for (int j = 0; j < 4; j++) {
            int i = tid + j * 256;
            float4 lv = l4[i], mm = m4[i];
            float s = (1.0f + lv.x - __expf(lv.x) - mm.x*mm.x)
                    + (1.0f + lv.y - __expf(lv.y) - mm.y*mm.y)
                    + (1.0f + lv.z - __expf(lv.z) - mm.z*mm.z)
                    + (1.0f + lv.w - __expf(lv.w) - mm.w*mm.w);
            acc += (double)s * K_KLD;
        }
        #pragma unroll
        for (int o = 16; o > 0; o >>= 1)
            acc += __shfl_down_sync(0xffffffffu, acc, o);
        if ((tid & 31) == 0) S.dred[tid >> 5] = acc;
        __syncthreads();
        if (tid < 32) {
            double v = (tid < 8) ? S.dred[tid] : 0.0;
            #pragma unroll
            for (int o = 4; o > 0; o >>= 1)
                v += __shfl_down_sync(0xffffffffu, v, o);
            if (tid == 0) q = __double2ll_rn(v * FXSCALE);
        }

    } else if (bid <= STFT_BLOCKS) {
        // =================== STFT path ===================
        const int sbid = bid - 1;
        const int b = sbid / 38;
        const int prow = sbid - b * 38;   // image rows prow*4 .. prow*4+11

        const float* pin  = xin  + ((long)b * 160 + (long)prow * 4) * 480;
        const float* pout = xout + ((long)b * 160 + (long)prow * 4) * 480;

        const ull p05 = pk(0.5f, 0.5f);
        const ull m05 = pk(-0.5f, -0.5f);
        const ull pS3 = pk(0.86602540378f, 0.86602540378f);

        // Phase A: ONE packed column DFT across (in,out) images (2-src packed
        // adds are a true 2x). Store (re, +g) per image.
        for (int e = tid; e < 480; e += 256) {
            ull v[12];
            #pragma unroll
            for (int y = 0; y < 12; y++)
                v[y] = pk(pin[y*480 + e], pout[y*480 + e]);
            ull hr[5], g[5];
            dft12_5_p(v, hr, g, p05, m05, pS3);
            #pragma unroll
            for (int u = 0; u < 5; u++) {
                float2 h = up2(hr[u]), gg = up2(g[u]);
                S.stft.Hin [u][e] = make_float2(h.x, gg.x);
                S.stft.Hout[u][e] = make_float2(h.y, gg.y);
            }
        }
        __syncthreads();

        // Phase B: 570 items. Packed DFT on (re,g) columns per image.
        // h = re - i*g. F.re = Pa - Gb; F.im = -(Ga + Pb)
        // where P = sum c*cos = (Pa,Pb), G = sum c*sin = (Ga,Gb).
        float acc = 0.f;
        for (int id = tid; id < 570; id += 256) {
            const int u = id / 114;       // 0..4  (bin u+1)
            const int m = id - u*114;     // 0..113 = j*3 + c
            const int cch = m % 3;
            const int e0 = 4*m - 3*cch;   // = 12j + c

            float Fir[5], Fii[5], For[5], Foi[5];
            {
                ull c[12];
                #pragma unroll
                for (int x = 0; x < 12; x++)
                    c[x] = *reinterpret_cast<const ull*>(&S.stft.Hin[u][e0 + 3*x]);
                ull P[5], G[5];
                dft12_5_p(c, P, G, p05, m05, pS3);
                #pragma unroll
                for (int v = 0; v < 5; v++) {
                    float2 pv = up2(P[v]), gv = up2(G[v]);
                    Fir[v] = pv.x - gv.y;
                    Fii[v] = -(gv.x + pv.y);
                }
            }
            {
                ull c[12];
                #pragma unroll
                for (int x = 0; x < 12; x++)
                    c[x] = *reinterpret_cast<const ull*>(&S.stft.Hout[u][e0 + 3*x]);
                ull P[5], G[5];
                dft12_5_p(c, P, G, p05, m05, pS3);
                #pragma unroll
                for (int v = 0; v < 5; v++) {
                    float2 pv = up2(P[v]), gv = up2(G[v]);
                    For[v] = pv.x - gv.y;
                    Foi[v] = -(gv.x + pv.y);
                }
            }

            const float wu = (float)(u + 1) * (1.f / 25.f);
            #pragma unroll
            for (int v = 1; v <= 5; v++) {
                const int vi = v - 1;
                float angi = fast_atan2f(Fii[vi], Fir[vi] + 1e-8f);
                float ango = fast_atan2f(Foi[vi], For[vi] + 1e-8f);
                float m2i = fmaf(Fir[vi], Fir[vi], Fii[vi]*Fii[vi]);
                float m2o = fmaf(For[vi], For[vi], Foi[vi]*Foi[vi]);
                float magi = fsqrt_approx(m2i);
                float mago = fsqrt_approx(m2o);
                acc = fmaf((float)v * wu, fabsf(ango - angi) + fabsf(mago - magi), acc);
            }
        }

        __syncthreads();                  // wred aliases H: all H reads must finish
        float tot = block_reduce_256(acc, S.wred, tid);
        if (tid == 0)
            q = __double2ll_rn((double)tot * (1e-4 / 32.0) * FXSCALE);

    } else {
        // =================== SSIM path ===================
        const int idx = bid - 1 - STFT_BLOCKS;
        const int bz = idx / 25;          // b*3 + c
        const int r25 = idx - bz*25;
        const int by = r25 / 5, bx = r25 - by*5;
        const int c  = bz % 3, b = bz / 3;
        const int ox = bx * 32, oy = by * 32;

        const float* pin  = xin  + (size_t)b * (160*160*3) + c;
        const float* pout = xout + (size_t)b * (160*160*3) + c;

        float val;
        if (bx < 4 && by < 4)
            val = ssim_tile<false>(S, pin, pout, ox, oy, tid);
        else
            val = ssim_tile<true >(S, pin, pout, ox, oy, tid);

        float tot = block_reduce_256(val, S.wred, tid);
        if (tid == 0)
            q = __double2ll_rn((double)tot * (1.0 / (32.0 * 150.0 * 150.0 * 3.0)) * FXSCALE);
    }

    // ---- publish + last-block finalize (tid 0 only) ----
    if (tid == 0) {
        atomicAdd(&g_acc, (unsigned long long)q);
        __threadfence();                  // order g_acc add before counter add
        unsigned int old = atomicAdd(&g_count, 1u);
        if (old == TOTAL_BLOCKS - 1) {    // I'm the last block
            unsigned long long raw = atomicExch(&g_acc, 0ULL);  // consume + reset
            out[0] = (float)((double)(long long)raw * (1.0 / FXSCALE));
            g_count = 0;                  // reset for next graph replay
        }
    }
}

// ---------------------------------------------------------------------------
extern "C" void kernel_launch(void* const* d_in, const int* in_sizes, int n_in,
                              void* d_out, int out_size)
{
    const float* mean   = (const float*)d_in[0];
    const float* logvar = (const float*)d_in[1];
    const float* xin    = (const float*)d_in[2];
    const float* xout   = (const float*)d_in[3];
    float* out = (float*)d_out;

    fused_kernel<<<TOTAL_BLOCKS, 256>>>(xin, xout, mean, logvar, out);
}